// round 14
// baseline (speedup 1.0000x reference)
#include <cuda_runtime.h>
#include <cuda_bf16.h>
#include <cstdint>

#define B 32
#define A 64
#define SLEN 256
#define H 128
#define RLEN 64
#define E 16
#define K3 (3 * H)
#define K4 (4 * H)

__device__ float g_s1[B * A * H];
__device__ float g_Cs[B * H * A];
__device__ float g_pooled[B * A * 2 * H];
__device__ float g_ragent[B * A * 2 * H];
__device__ float g_s2[B * A * H];
__device__ float g_aeT[B * 2 * H * A];     // [b][c(256)][j(64)]
__device__ __align__(16) uint4 g_w1fh[8 * 4 * 32],   g_w1fl[8 * 4 * 32];
__device__ __align__(16) uint4 g_w2fh[16 * 8 * 32],  g_w2fl[16 * 8 * 32];
__device__ __align__(16) uint4 g_wrfh[8 * 24 * 32],  g_wrfl[8 * 24 * 32];
__device__ __align__(16) uint4 g_wa1fh[8 * 32 * 32], g_wa1fl[8 * 32 * 32];
__device__ __align__(16) uint4 g_wa2fh[16 * 8 * 32], g_wa2fl[16 * 8 * 32];

#define MMA4(d, a, b0, b1) asm volatile( \
    "mma.sync.aligned.m16n8k16.row.col.f32.bf16.bf16.f32 " \
    "{%0,%1,%2,%3},{%4,%5,%6,%7},{%8,%9},{%0,%1,%2,%3};" \
    : "+f"((d)[0]), "+f"((d)[1]), "+f"((d)[2]), "+f"((d)[3]) \
    : "r"((a)[0]), "r"((a)[1]), "r"((a)[2]), "r"((a)[3]), "r"(b0), "r"(b1))
#define LDSM4(r, a) asm volatile( \
    "ldmatrix.sync.aligned.m8n8.x4.shared.b16 {%0,%1,%2,%3}, [%4];" \
    : "=r"((r)[0]), "=r"((r)[1]), "=r"((r)[2]), "=r"((r)[3]) : "r"(a))
#define LDSM4T(r, a) asm volatile( \
    "ldmatrix.sync.aligned.m8n8.x4.trans.shared.b16 {%0,%1,%2,%3}, [%4];" \
    : "=r"((r)[0]), "=r"((r)[1]), "=r"((r)[2]), "=r"((r)[3]) : "r"(a))

__device__ __forceinline__ uint32_t s2u(const void* p) {
    uint32_t a;
    asm("{ .reg .u64 t; cvta.to.shared.u64 t, %1; cvt.u32.u64 %0, t; }" : "=r"(a) : "l"(p));
    return a;
}
__device__ __forceinline__ uint32_t pkhi(float a, float b) {
    __nv_bfloat162 t = __halves2bfloat162(__float2bfloat16(a), __float2bfloat16(b));
    return *reinterpret_cast<uint32_t*>(&t);
}
__device__ __forceinline__ uint32_t pklo(float a, float b) {
    float ra = a - __bfloat162float(__float2bfloat16(a));
    float rb = b - __bfloat162float(__float2bfloat16(b));
    __nv_bfloat162 t = __halves2bfloat162(__float2bfloat16(ra), __float2bfloat16(rb));
    return *reinterpret_cast<uint32_t*>(&t);
}
__device__ __forceinline__ void pack_frag(const float* W, int N, int r0, int ka,
                                          uint4* dh, uint4* dl) {
    float v00 = W[ka * N + r0],       v01 = W[(ka + 1) * N + r0];
    float v10 = W[ka * N + r0 + 8],   v11 = W[(ka + 1) * N + r0 + 8];
    float v20 = W[(ka + 8) * N + r0], v21 = W[(ka + 9) * N + r0];
    float v30 = W[(ka + 8) * N + r0 + 8], v31 = W[(ka + 9) * N + r0 + 8];
    *dh = make_uint4(pkhi(v00, v01), pkhi(v10, v11), pkhi(v20, v21), pkhi(v30, v31));
    *dl = make_uint4(pklo(v00, v01), pklo(v10, v11), pklo(v20, v21), pklo(v30, v31));
}

// ---------------- k_enc_prep ----------------
__global__ __launch_bounds__(256) void k_enc_prep(
    const float* __restrict__ st, const float* __restrict__ w1, const float* __restrict__ b1,
    const float* __restrict__ w2, const float* __restrict__ b2,
    const float* __restrict__ rw1, const float* __restrict__ rw2,
    const float* __restrict__ raw, const float* __restrict__ aw1, const float* __restrict__ aw2)
{
    __shared__ float X[4 * SLEN];
    __shared__ float HD[4 * H];
    __shared__ float RED[2 * 4 * H];
    const int t = threadIdx.x;

    if (blockIdx.x >= 512) {
        int it = (blockIdx.x - 512) * 256 + t;
        if (it < 1024) {
            const int i = it, lane = i & 31, ks = (i >> 5) & 3, slot = i >> 7;
            pack_frag(rw1, 128, slot * 16 + (lane >> 2), ks * 16 + 2 * (lane & 3),
                      &g_w1fh[i], &g_w1fl[i]);
        } else if (it < 5120) {
            const int i = it - 1024, lane = i & 31, ks = (i >> 5) & 7, slot = i >> 8;
            pack_frag(rw2, 256, slot * 16 + (lane >> 2), ks * 16 + 2 * (lane & 3),
                      &g_w2fh[i], &g_w2fl[i]);
        } else if (it < 11264) {
            const int i = it - 5120, lane = i & 31, ks = (i >> 5) % 24, slot = i / 768;
            pack_frag(raw, 128, slot * 16 + (lane >> 2), ks * 16 + 2 * (lane & 3),
                      &g_wrfh[i], &g_wrfl[i]);
        } else if (it < 19456) {
            const int i = it - 11264, lane = i & 31, ks = (i >> 5) & 31, slot = i >> 10;
            pack_frag(aw1, 128, slot * 16 + (lane >> 2), ks * 16 + 2 * (lane & 3),
                      &g_wa1fh[i], &g_wa1fl[i]);
        } else {
            const int i = it - 19456, lane = i & 31, ks = (i >> 5) & 7, slot = i >> 8;
            pack_frag(aw2, 256, slot * 16 + (lane >> 2), ks * 16 + 2 * (lane & 3),
                      &g_wa2fh[i], &g_wa2fl[i]);
        }
        return;
    }

    const int row0 = blockIdx.x * 4;
    for (int i = t; i < 4 * SLEN; i += 256) X[i] = st[(size_t)row0 * SLEN + i];
    __syncthreads();
    const int h = t & 127, kh = t >> 7;
    {
        float acc[4] = {0.f, 0.f, 0.f, 0.f};
        const float4* X4 = (const float4*)X;
        const int k0 = kh * 128;
#pragma unroll 4
        for (int k = k0; k < k0 + 128; k += 4) {
            float w0 = w1[k * H + h], wA = w1[(k + 1) * H + h], wB = w1[(k + 2) * H + h], wC = w1[(k + 3) * H + h];
#pragma unroll
            for (int j = 0; j < 4; j++) {
                float4 x = X4[j * (SLEN / 4) + (k >> 2)];
                acc[j] = fmaf(x.x, w0, acc[j]); acc[j] = fmaf(x.y, wA, acc[j]);
                acc[j] = fmaf(x.z, wB, acc[j]); acc[j] = fmaf(x.w, wC, acc[j]);
            }
        }
#pragma unroll
        for (int j = 0; j < 4; j++) RED[(kh * 4 + j) * H + h] = acc[j];
    }
    __syncthreads();
    for (int idx = t; idx < 4 * H; idx += 256)
        HD[idx] = fmaxf(RED[idx] + RED[4 * H + idx] + b1[idx & 127], 0.f);
    __syncthreads();
    {
        const int rb = kh * 2;
        float acc[2];
        const float bb = b2[h];
        acc[0] = bb; acc[1] = bb;
        const float4* H4 = (const float4*)HD;
#pragma unroll 4
        for (int k = 0; k < H; k += 4) {
            float w0 = w2[k * H + h], wA = w2[(k + 1) * H + h], wB = w2[(k + 2) * H + h], wC = w2[(k + 3) * H + h];
#pragma unroll
            for (int j = 0; j < 2; j++) {
                float4 x = H4[(rb + j) * (H / 4) + (k >> 2)];
                acc[j] = fmaf(x.x, w0, acc[j]); acc[j] = fmaf(x.y, wA, acc[j]);
                acc[j] = fmaf(x.z, wB, acc[j]); acc[j] = fmaf(x.w, wC, acc[j]);
            }
        }
#pragma unroll
        for (int j = 0; j < 2; j++) g_s1[(size_t)(row0 + rb + j) * H + h] = fmaxf(acc[j], 0.f);
    }
}

// ---------------- k_smm ----------------
__global__ __launch_bounds__(256) void k_smm(const float* __restrict__ w1)
{
    __shared__ float S[16 * 128];
    const int b = blockIdx.x >> 2, j0 = (blockIdx.x & 3) * 16, t = threadIdx.x;
    for (int i = t; i < 16 * 128; i += 256)
        S[i] = g_s1[(size_t)b * 8192 + (size_t)j0 * 128 + i];
    __syncthreads();
    const int c = t & 127, jh = t >> 7;
    float acc[8];
#pragma unroll
    for (int j = 0; j < 8; j++) acc[j] = 0.f;
    const float4* S4 = (const float4*)S;
#pragma unroll 2
    for (int k4 = 0; k4 < 32; k4++) {
        const int k = 4 * k4;
        float w0 = w1[(64 + k) * 128 + c], wA = w1[(65 + k) * 128 + c];
        float wB = w1[(66 + k) * 128 + c], wC = w1[(67 + k) * 128 + c];
#pragma unroll
        for (int j = 0; j < 8; j++) {
            float4 s = S4[(jh * 8 + j) * 32 + k4];
            acc[j] = fmaf(s.x, w0, acc[j]); acc[j] = fmaf(s.y, wA, acc[j]);
            acc[j] = fmaf(s.z, wB, acc[j]); acc[j] = fmaf(s.w, wC, acc[j]);
        }
    }
#pragma unroll
    for (int j = 0; j < 8; j++)
        g_Cs[(size_t)b * 8192 + c * 64 + j0 + jh * 8 + j] = acc[j];
}

// ---------------- k_rel: round-robin accumulator MMA order ----------------
#define XS 72
#define HTS 72
#define SM_REL 55552

// interleaved: term-k for both accs before term-k+1 (breaks RAW chains)
#define DO6(q, BH, BL) \
    MMA4(ac[q], ah, BH[0], BH[1]);     MMA4(ac[q + 1], ah, BH[2], BH[3]); \
    MMA4(ac[q], ah, BL[0], BL[1]);     MMA4(ac[q + 1], ah, BL[2], BL[3]); \
    MMA4(ac[q], alr, BH[0], BH[1]);    MMA4(ac[q + 1], alr, BH[2], BH[3]);

#define DO12(q, BH, BL) \
    MMA4(acM[q], aha, BH[0], BH[1]);   MMA4(acX[q], ahb, BH[0], BH[1]); \
    MMA4(acM[q + 1], aha, BH[2], BH[3]); MMA4(acX[q + 1], ahb, BH[2], BH[3]); \
    MMA4(acM[q], aha, BL[0], BL[1]);   MMA4(acX[q], ahb, BL[0], BL[1]); \
    MMA4(acM[q + 1], aha, BL[2], BL[3]); MMA4(acX[q + 1], ahb, BL[2], BL[3]); \
    MMA4(acM[q], ala, BH[0], BH[1]);   MMA4(acX[q], alb, BH[0], BH[1]); \
    MMA4(acM[q + 1], ala, BH[2], BH[3]); MMA4(acX[q + 1], alb, BH[2], BH[3]);

__global__ __launch_bounds__(256, 2) void k_rel(
    const float* __restrict__ rel, const float* __restrict__ alive,
    const float* __restrict__ b1, const float* __restrict__ b2,
    const int* __restrict__ agp)
{
    extern __shared__ unsigned char smem[];
    __nv_bfloat16* XH = (__nv_bfloat16*)smem;
    __nv_bfloat16* XL = (__nv_bfloat16*)(smem + 9216);
    __nv_bfloat16* HTh = (__nv_bfloat16*)(smem + 18432);
    __nv_bfloat16* HTl = (__nv_bfloat16*)(smem + 36864);
    float* sal = (float*)(smem + 55296);

    const int tid = threadIdx.x, w = tid >> 5, l = tid & 31, g = l >> 2, t4 = l & 3;
    const int bi = blockIdx.x, b = bi >> 6, i = bi & 63;
    if (tid < 64) sal[tid] = alive[b * 64 + tid];

    const int sel = l >> 3, lr = l & 7;
    const uint32_t xrow = (uint32_t)(((lr + ((sel >> 1) << 3)) * XS + ((sel & 1) << 3)) * 2);
    const uint32_t hrow = (uint32_t)(((lr + ((sel & 1) << 3)) * HTS + ((sel >> 1) << 3)) * 2);
    const uint32_t xh_b = s2u(XH), xl_b = s2u(XL), hh_b = s2u(HTh), hl_b = s2u(HTl);

    {
        const float4* rr4 = (const float4*)(rel + (size_t)bi * 4096);
        for (int idx = tid; idx < 1024; idx += 256) {
            const int j = idx >> 4, k4 = idx & 15;
            float4 v = rr4[idx];
            *(uint2*)(XH + j * XS + k4 * 4) = make_uint2(pkhi(v.x, v.y), pkhi(v.z, v.w));
            *(uint2*)(XL + j * XS + k4 * 4) = make_uint2(pklo(v.x, v.y), pklo(v.z, v.w));
        }
    }
    const int r0 = w * 16 + g;
    float2 csA[8], csB[8];
    {
        const float* pA = g_Cs + (size_t)b * 8192 + r0 * 64;
        const float* pB = pA + 8 * 64;
#pragma unroll
        for (int n = 0; n < 8; n++) {
            csA[n] = *(const float2*)(pA + n * 8 + 2 * t4);
            csB[n] = *(const float2*)(pB + n * 8 + 2 * t4);
        }
    }
    __syncthreads();

    float ac[8][4];
#pragma unroll
    for (int n = 0; n < 8; n++) { ac[n][0] = 0.f; ac[n][1] = 0.f; ac[n][2] = 0.f; ac[n][3] = 0.f; }
#pragma unroll
    for (int ks = 0; ks < 4; ks++) {
        const uint4 AH = g_w1fh[(w * 4 + ks) * 32 + l];
        const uint4 AL = g_w1fl[(w * 4 + ks) * 32 + l];
        const uint32_t ah[4] = {AH.x, AH.y, AH.z, AH.w};
        const uint32_t alr[4] = {AL.x, AL.y, AL.z, AL.w};
        const uint32_t kb = (uint32_t)(ks * 32);
        uint32_t bh0[4], bl0[4], bh1[4], bl1[4];
        LDSM4(bh0, xh_b + kb + xrow);
        LDSM4(bl0, xl_b + kb + xrow);
        LDSM4(bh1, xh_b + (uint32_t)(16 * XS * 2) + kb + xrow);
        LDSM4(bl1, xl_b + (uint32_t)(16 * XS * 2) + kb + xrow);
        DO6(0, bh0, bl0)
        DO6(2, bh1, bl1)
        LDSM4(bh0, xh_b + (uint32_t)(32 * XS * 2) + kb + xrow);
        LDSM4(bl0, xl_b + (uint32_t)(32 * XS * 2) + kb + xrow);
        LDSM4(bh1, xh_b + (uint32_t)(48 * XS * 2) + kb + xrow);
        LDSM4(bl1, xl_b + (uint32_t)(48 * XS * 2) + kb + xrow);
        DO6(4, bh0, bl0)
        DO6(6, bh1, bl1)
    }
    {
        const float bA = b1[r0], bB = b1[r0 + 8];
#pragma unroll
        for (int n = 0; n < 8; n++) {
            const int j0 = n * 8 + 2 * t4;
            float v0 = fmaxf(ac[n][0] + csA[n].x + bA, 0.f);
            float v1 = fmaxf(ac[n][1] + csA[n].y + bA, 0.f);
            float v2 = fmaxf(ac[n][2] + csB[n].x + bB, 0.f);
            float v3 = fmaxf(ac[n][3] + csB[n].y + bB, 0.f);
            *(uint32_t*)(HTh + r0 * HTS + j0) = pkhi(v0, v1);
            *(uint32_t*)(HTl + r0 * HTS + j0) = pklo(v0, v1);
            *(uint32_t*)(HTh + (r0 + 8) * HTS + j0) = pkhi(v2, v3);
            *(uint32_t*)(HTl + (r0 + 8) * HTS + j0) = pklo(v2, v3);
        }
    }
    __syncthreads();

    float acM[8][4], acX[8][4];
#pragma unroll
    for (int n = 0; n < 8; n++) {
        acM[n][0] = 0.f; acM[n][1] = 0.f; acM[n][2] = 0.f; acM[n][3] = 0.f;
        acX[n][0] = 0.f; acX[n][1] = 0.f; acX[n][2] = 0.f; acX[n][3] = 0.f;
    }
#pragma unroll 1
    for (int ks = 0; ks < 8; ks++) {
        const uint4 AHa = g_w2fh[(w * 8 + ks) * 32 + l];
        const uint4 ALa = g_w2fl[(w * 8 + ks) * 32 + l];
        const uint4 AHb = g_w2fh[((8 + w) * 8 + ks) * 32 + l];
        const uint4 ALb = g_w2fl[((8 + w) * 8 + ks) * 32 + l];
        const uint32_t aha[4] = {AHa.x, AHa.y, AHa.z, AHa.w};
        const uint32_t ala[4] = {ALa.x, ALa.y, ALa.z, ALa.w};
        const uint32_t ahb[4] = {AHb.x, AHb.y, AHb.z, AHb.w};
        const uint32_t alb[4] = {ALb.x, ALb.y, ALb.z, ALb.w};
        const uint32_t kb = (uint32_t)(ks * 16 * HTS * 2);
        uint32_t bh0[4], bl0[4], bh1[4], bl1[4];
        LDSM4T(bh0, hh_b + kb + hrow);
        LDSM4T(bl0, hl_b + kb + hrow);
        LDSM4T(bh1, hh_b + kb + 32 + hrow);
        LDSM4T(bl1, hl_b + kb + 32 + hrow);
        DO12(0, bh0, bl0)
        DO12(2, bh1, bl1)
        LDSM4T(bh0, hh_b + kb + 64 + hrow);
        LDSM4T(bl0, hl_b + kb + 64 + hrow);
        LDSM4T(bh1, hh_b + kb + 96 + hrow);
        LDSM4T(bl1, hl_b + kb + 96 + hrow);
        DO12(4, bh0, bl0)
        DO12(6, bh1, bl1)
    }
    {
        const int rrA = w * 16 + g;
        const int rrB = 128 + w * 16 + g;
        const int gag = *agp;
        const bool isag = (i == gag);
        const float bMA = b2[rrA], bMB = b2[rrA + 8];
        const float bXA = b2[rrB], bXB = b2[rrB + 8];
        float s0 = 0.f, s1 = 0.f, t0 = 0.f, t1 = 0.f;
        float* rg = g_ragent + (size_t)(b * 64) * 256;
#pragma unroll
        for (int n = 0; n < 8; n++) {
            const int j0 = n * 8 + 2 * t4;
            const float al0 = sal[j0], al1 = sal[j0 + 1];
            float m0 = fmaxf(acM[n][0] + bMA, 0.f), m1 = fmaxf(acM[n][1] + bMA, 0.f);
            float m2 = fmaxf(acM[n][2] + bMB, 0.f), m3 = fmaxf(acM[n][3] + bMB, 0.f);
            float x0 = fmaxf(acX[n][0] + bXA, 0.f), x1 = fmaxf(acX[n][1] + bXA, 0.f);
            float x2 = fmaxf(acX[n][2] + bXB, 0.f), x3 = fmaxf(acX[n][3] + bXB, 0.f);
            if (isag) {
                rg[(size_t)j0 * 256 + rrA] = m0;
                rg[(size_t)(j0 + 1) * 256 + rrA] = m1;
                rg[(size_t)j0 * 256 + rrA + 8] = m2;
                rg[(size_t)(j0 + 1) * 256 + rrA + 8] = m3;
                rg[(size_t)j0 * 256 + rrB] = x0;
                rg[(size_t)(j0 + 1) * 256 + rrB] = x1;
                rg[(size_t)j0 * 256 + rrB + 8] = x2;
                rg[(size_t)(j0 + 1) * 256 + rrB + 8] = x3;
            }
            s0 += m0 * al0 + m1 * al1;
            s1 += m2 * al0 + m3 * al1;
            t0 = fmaxf(t0, fmaxf(x0 * al0, x1 * al1));
            t1 = fmaxf(t1, fmaxf(x2 * al0, x3 * al1));
        }
        s0 += __shfl_xor_sync(0xffffffffu, s0, 1); s0 += __shfl_xor_sync(0xffffffffu, s0, 2);
        s1 += __shfl_xor_sync(0xffffffffu, s1, 1); s1 += __shfl_xor_sync(0xffffffffu, s1, 2);
        t0 = fmaxf(t0, __shfl_xor_sync(0xffffffffu, t0, 1)); t0 = fmaxf(t0, __shfl_xor_sync(0xffffffffu, t0, 2));
        t1 = fmaxf(t1, __shfl_xor_sync(0xffffffffu, t1, 1)); t1 = fmaxf(t1, __shfl_xor_sync(0xffffffffu, t1, 2));
        if (t4 == 0) {
            g_pooled[(size_t)bi * 256 + rrA] = s0 * (1.f / 64.f);
            g_pooled[(size_t)bi * 256 + rrA + 8] = s1 * (1.f / 64.f);
            g_pooled[(size_t)bi * 256 + rrB] = t0;
            g_pooled[(size_t)bi * 256 + rrB + 8] = t1;
        }
    }
}

// ---------------- k_tail: 512 thr, split-K warp pairs, prefetch, RR MMA order ----------------
#define XT 520
#define S2S 132
#define HT2 24
#define SM_TAIL 88848

__global__ __launch_bounds__(512, 1) void k_tail(
    const float* __restrict__ raw, const float* __restrict__ rab,
    const float* __restrict__ ab1, const float* __restrict__ ab2,
    const int* __restrict__ agp)
{
    extern __shared__ unsigned char smem[];
    __nv_bfloat16* XH = (__nv_bfloat16*)smem;
    __nv_bfloat16* XL = (__nv_bfloat16*)(smem + 16640);
    float* S2f = (float*)(smem + 33280);
    __nv_bfloat16* HTh = (__nv_bfloat16*)(smem + 42256);
    __nv_bfloat16* HTl = (__nv_bfloat16*)(smem + 48400);
    float* RED = (float*)(smem + 54544);
    float* AG = (float*)(smem + 87312);

    const int tid = threadIdx.x, w = tid >> 5, l = tid & 31, g = l >> 2, t4 = l & 3;
    const int wp = w & 7, kh2 = w >> 3;
    const int b = blockIdx.x >> 2, jg0 = (blockIdx.x & 3) * 16;
    const int gag = *agp;
    const int sel = l >> 3, lr = l & 7;
    const uint32_t xrow = (uint32_t)(((lr + ((sel >> 1) << 3)) * XT + ((sel & 1) << 3)) * 2);
    const uint32_t hrow = (uint32_t)(((lr + ((sel & 1) << 3)) * HT2 + ((sel >> 1) << 3)) * 2);
    const uint32_t xh_b = s2u(XH), xl_b = s2u(XL), hh_b = s2u(HTh), hl_b = s2u(HTl);
    const int r0 = wp * 16 + g;
    const int j0 = 2 * t4, j1 = 8 + 2 * t4;

    for (int idx = tid; idx < 16 * 32; idx += 512) {
        const int j = idx >> 5, k4 = idx & 31;
        float4 v = *(const float4*)(g_s1 + (size_t)(b * 64 + jg0 + j) * 128 + k4 * 4);
        *(uint2*)(XH + j * XT + k4 * 4) = make_uint2(pkhi(v.x, v.y), pkhi(v.z, v.w));
        *(uint2*)(XL + j * XT + k4 * 4) = make_uint2(pklo(v.x, v.y), pklo(v.z, v.w));
    }
    for (int idx = tid; idx < 16 * 64; idx += 512) {
        const int j = idx >> 6, k4 = idx & 63;
        float4 v = *(const float4*)(g_pooled + (size_t)(b * 64 + j + jg0) * 256 + k4 * 4);
        *(uint2*)(XH + j * XT + 128 + k4 * 4) = make_uint2(pkhi(v.x, v.y), pkhi(v.z, v.w));
        *(uint2*)(XL + j * XT + 128 + k4 * 4) = make_uint2(pklo(v.x, v.y), pklo(v.z, v.w));
    }
    if (tid < 96) {
        float4 v = (tid < 32)
            ? *(const float4*)(g_s1 + (size_t)(b * 64 + gag) * 128 + tid * 4)
            : *(const float4*)(g_pooled + (size_t)(b * 64 + gag) * 256 + (tid - 32) * 4);
        *(float4*)(AG + tid * 4) = v;
    }
    __syncthreads();

    // ---- ra GEMM: K=384, 12 ks per warp-half, prefetched, RR order ----
    {
        float a0[4] = {0.f, 0.f, 0.f, 0.f}, a1[4] = {0.f, 0.f, 0.f, 0.f};
        const int ks0 = kh2 * 12;
        uint4 AH = g_wrfh[(wp * 24 + ks0) * 32 + l];
        uint4 AL = g_wrfl[(wp * 24 + ks0) * 32 + l];
#pragma unroll 1
        for (int ks = ks0; ks < ks0 + 12; ks++) {
            uint4 AHn = AH, ALn = AL;
            if (ks + 1 < ks0 + 12) {
                AHn = g_wrfh[(wp * 24 + ks + 1) * 32 + l];
                ALn = g_wrfl[(wp * 24 + ks + 1) * 32 + l];
            }
            const uint32_t ah[4] = {AH.x, AH.y, AH.z, AH.w};
            const uint32_t alr[4] = {AL.x, AL.y, AL.z, AL.w};
            uint32_t bh[4], bl[4];
            LDSM4(bh, xh_b + (uint32_t)(ks * 32) + xrow);
            LDSM4(bl, xl_b + (uint32_t)(ks * 32) + xrow);
            MMA4(a0, ah, bh[0], bh[1]);  MMA4(a1, ah, bh[2], bh[3]);
            MMA4(a0, ah, bl[0], bl[1]);  MMA4(a1, ah, bl[2], bl[3]);
            MMA4(a0, alr, bh[0], bh[1]); MMA4(a1, alr, bh[2], bh[3]);
            AH = AHn; AL = ALn;
        }
        float* RP = RED + kh2 * 2048;
        RP[j0 * 128 + r0] = a0[0];       RP[(j0 + 1) * 128 + r0] = a0[1];
        RP[j0 * 128 + r0 + 8] = a0[2];   RP[(j0 + 1) * 128 + r0 + 8] = a0[3];
        RP[j1 * 128 + r0] = a1[0];       RP[(j1 + 1) * 128 + r0] = a1[1];
        RP[j1 * 128 + r0 + 8] = a1[2];   RP[(j1 + 1) * 128 + r0 + 8] = a1[3];
    }
    {
        const int h = tid & 127, kh = tid >> 7;
        float acc = 0.f;
        const int k0 = kh * 96;
#pragma unroll 4
        for (int k = k0; k < k0 + 96; k++)
            acc = fmaf(AG[k], raw[k * 128 + h], acc);
        RED[4096 + kh * 128 + h] = acc;
    }
    __syncthreads();
    for (int idx = tid; idx < 2048; idx += 512) {
        const int c = idx >> 4, j = idx & 15;
        S2f[j * S2S + c] = fmaxf(RED[j * 128 + c] + RED[2048 + j * 128 + c] + rab[c], 0.f);
    }
    if (tid < 128)
        S2f[16 * S2S + tid] = fmaxf(RED[4096 + tid] + RED[4224 + tid]
                                  + RED[4352 + tid] + RED[4480 + tid] + rab[tid], 0.f);
    __syncthreads();

    for (int idx = tid; idx < 16 * 64; idx += 512) {
        const int j = idx >> 6, k4 = idx & 63;
        float4 v = *(const float4*)(g_ragent + (size_t)(b * 64 + jg0 + j) * 256 + k4 * 4);
        *(uint2*)(XH + j * XT + k4 * 4) = make_uint2(pkhi(v.x, v.y), pkhi(v.z, v.w));
        *(uint2*)(XL + j * XT + k4 * 4) = make_uint2(pklo(v.x, v.y), pklo(v.z, v.w));
    }
    for (int idx = tid; idx < 16 * 32; idx += 512) {
        const int j = idx >> 5, k4 = idx & 31;
        float4 v = *(const float4*)(S2f + j * S2S + k4 * 4);
        *(uint2*)(XH + j * XT + 256 + k4 * 4) = make_uint2(pkhi(v.x, v.y), pkhi(v.z, v.w));
        *(uint2*)(XL + j * XT + 256 + k4 * 4) = make_uint2(pklo(v.x, v.y), pklo(v.z, v.w));
        *(float4*)(g_s2 + (size_t)(b * 64 + jg0 + j) * 128 + k4 * 4) = v;
        float4 va = *(const float4*)(S2f + 16 * S2S + k4 * 4);
        *(uint2*)(XH + j * XT + 384 + k4 * 4) = make_uint2(pkhi(va.x, va.y), pkhi(va.z, va.w));
        *(uint2*)(XL + j * XT + 384 + k4 * 4) = make_uint2(pklo(va.x, va.y), pklo(va.z, va.w));
    }
    __syncthreads();

    // ---- ae layer 1: K=512, 16 ks per warp-half, prefetched, RR order ----
    {
        float a0[4] = {0.f, 0.f, 0.f, 0.f}, a1[4] = {0.f, 0.f, 0.f, 0.f};
        const int ks0 = kh2 * 16;
        uint4 AH = g_wa1fh[(wp * 32 + ks0) * 32 + l];
        uint4 AL = g_wa1fl[(wp * 32 + ks0) * 32 + l];
#pragma unroll 1
        for (int ks = ks0; ks < ks0 + 16; ks++) {
            uint4 AHn = AH, ALn = AL;
            if (ks + 1 < ks0 + 16) {
                AHn = g_wa1fh[(wp * 32 + ks + 1) * 32 + l];
                ALn = g_wa1fl[(wp * 32 + ks + 1) * 32 + l];
            }
            const uint32_t ah[4] = {AH.x, AH.y, AH.z, AH.w};
            const uint32_t alr[4] = {AL.x, AL.y, AL.z, AL.w};
            uint32_t bh[4], bl[4];
            LDSM4(bh, xh_b + (uint32_t)(ks * 32) + xrow);
            LDSM4(bl, xl_b + (uint32_t)(ks * 32) + xrow);
            MMA4(a0, ah, bh[0], bh[1]);  MMA4(a1, ah, bh[2], bh[3]);
            MMA4(a0, ah, bl[0], bl[1]);  MMA4(a1, ah, bl[2], bl[3]);
            MMA4(a0, alr, bh[0], bh[1]); MMA4(a1, alr, bh[2], bh[3]);
            AH = AHn; AL = ALn;
        }
        float* RP = RED + kh2 * 2048;
        RP[j0 * 128 + r0] = a0[0];       RP[(j0 + 1) * 128 + r0] = a0[1];
        RP[j0 * 128 + r0 + 8] = a0[2];   RP[(j0 + 1) * 128 + r0 + 8] = a0[3];
        RP[j1 * 128 + r0] = a1[0];       RP[(j1 + 1) * 128 + r0] = a1[1];
        RP[j1 * 128 + r0 + 8] = a1[2];   RP[(j1 + 1) * 128 + r0 + 8] = a1[3];
    }
    __syncthreads();
    for (int idx = tid; idx < 2048; idx += 512) {
        const int c = idx >> 4, j = idx & 15;
        float v = fmaxf(RED[j * 128 + c] + RED[2048 + j * 128 + c] + ab1[c], 0.f);
        __nv_bfloat16 hh = __float2bfloat16(v);
        HTh[c * HT2 + j] = hh;
        HTl[c * HT2 + j] = __float2bfloat16(v - __bfloat162float(hh));
    }
    __syncthreads();

    // ---- ae layer 2: K=128, 4 ks per warp-half, prefetched, RR order ----
    {
        float acM0[4] = {0.f, 0.f, 0.f, 0.f}, acM1[4] = {0.f, 0.f, 0.f, 0.f};
        float acX0[4] = {0.f, 0.f, 0.f, 0.f}, acX1[4] = {0.f, 0.f, 0.f, 0.f};
        const int ks0 = kh2 * 4;
        uint4 AHa = g_wa2fh[(wp * 8 + ks0) * 32 + l];
        uint4 ALa = g_wa2fl[(wp * 8 + ks0) * 32 + l];
        uint4 AHb = g_wa2fh[((8 + wp) * 8 + ks0) * 32 + l];
        uint4 ALb = g_wa2fl[((8 + wp) * 8 + ks0) * 32 + l];
#pragma unroll 1
        for (int ks = ks0; ks < ks0 + 4; ks++) {
            uint4 AHan = AHa, ALan = ALa, AHbn = AHb, ALbn = ALb;
            if (ks + 1 < ks0 + 4) {
                AHan = g_wa2fh[(wp * 8 + ks + 1) * 32 + l];
                ALan = g_wa2fl[(wp * 8 + ks + 1) * 32 + l];
                AHbn = g_wa2fh[((8 + wp) * 8 + ks + 1) * 32 + l];
                ALbn = g_wa2fl[((8 + wp) * 8 + ks + 1) * 32 + l];
            }
            const uint32_t aha[4] = {AHa.x, AHa.y, AHa.z, AHa.w};
            const uint32_t ala[4] = {ALa.x, ALa.y, ALa.z, ALa.w};
            const uint32_t ahb[4] = {AHb.x, AHb.y, AHb.z, AHb.w};
            const uint32_t alb[4] = {ALb.x, ALb.y, ALb.z, ALb.w};
            uint32_t bh[4], bl[4];
            LDSM4T(bh, hh_b + (uint32_t)(ks * 16 * HT2 * 2) + hrow);
            LDSM4T(bl, hl_b + (uint32_t)(ks * 16 * HT2 * 2) + hrow);
            MMA4(acM0, aha, bh[0], bh[1]);  MMA4(acX0, ahb, bh[0], bh[1]);
            MMA4(acM1, aha, bh[2], bh[3]);  MMA4(acX1, ahb, bh[2], bh[3]);
            MMA4(acM0, aha, bl[0], bl[1]);  MMA4(acX0, ahb, bl[0], bl[1]);
            MMA4(acM1, aha, bl[2], bl[3]);  MMA4(acX1, ahb, bl[2], bl[3]);
            MMA4(acM0, ala, bh[0], bh[1]);  MMA4(acX0, alb, bh[0], bh[1]);
            MMA4(acM1, ala, bh[2], bh[3]);  MMA4(acX1, alb, bh[2], bh[3]);
            AHa = AHan; ALa = ALan; AHb = AHbn; ALb = ALbn;
        }
        float* RP = RED + kh2 * 4096;
        RP[j0 * 256 + r0] = acM0[0];         RP[(j0 + 1) * 256 + r0] = acM0[1];
        RP[j0 * 256 + r0 + 8] = acM0[2];     RP[(j0 + 1) * 256 + r0 + 8] = acM0[3];
        RP[j1 * 256 + r0] = acM1[0];         RP[(j1 + 1) * 256 + r0] = acM1[1];
        RP[j1 * 256 + r0 + 8] = acM1[2];     RP[(j1 + 1) * 256 + r0 + 8] = acM1[3];
        RP[j0 * 256 + 128 + r0] = acX0[0];   RP[(j0 + 1) * 256 + 128 + r0] = acX0[1];
        RP[j0 * 256 + 128 + r0 + 8] = acX0[2]; RP[(j0 + 1) * 256 + 128 + r0 + 8] = acX0[3];
        RP[j1 * 256 + 128 + r0] = acX1[0];   RP[(j1 + 1) * 256 + 128 + r0] = acX1[1];
        RP[j1 * 256 + 128 + r0 + 8] = acX1[2]; RP[(j1 + 1) * 256 + 128 + r0 + 8] = acX1[3];
    }
    __syncthreads();
    {
        float* ae = g_aeT + (size_t)b * 256 * 64 + jg0;
        for (int idx = tid; idx < 4096; idx += 512) {
            const int c = idx >> 4, j = idx & 15;
            float v = fmaxf(RED[j * 256 + c] + RED[4096 + j * 256 + c] + ab2[c], 0.f);
            ae[c * 64 + j] = v;
        }
    }
}

// ---------------- k_final (g_aeT layout) ----------------
__global__ __launch_bounds__(256) void k_final(
    const float* __restrict__ action_embed, const int* __restrict__ action,
    const int* __restrict__ agp, float* __restrict__ out)
{
    const int b = blockIdx.x, t = threadIdx.x;
    const int h = t & 127, jp = t >> 7;
    const int a = action[b], g = *agp;
    const float sel = (a < E) ? action_embed[a * H + h]
                              : g_aeT[((size_t)b * 256 + h) * 64 + (a - E)];
    float* out_state = out;
    float* out_sel = out + (size_t)B * A * H;
    float* out_ps = out_sel + (size_t)B * H;
    if (jp == 0) out_sel[b * H + h] = sel;
    for (int j = jp; j < A; j += 2) {
        float st = g_s2[((size_t)b * A + j) * H + h];
        float ps = 0.f;
        if (a == E + j) ps = g_aeT[((size_t)b * 256 + H + h) * 64 + j];
        if (j == g) st += sel;
        out_ps[((size_t)b * A + j) * H + h] = ps;
        out_state[((size_t)b * A + j) * H + h] = st + ps;
    }
}

// ---------------- launcher ----------------
extern "C" void kernel_launch(void* const* d_in, const int* in_sizes, int n_in,
                              void* d_out, int out_size)
{
    const float* states       = (const float*)d_in[0];
    const float* relations    = (const float*)d_in[1];
    const float* alive_mask   = (const float*)d_in[2];
    const float* se_w1        = (const float*)d_in[3];
    const float* se_b1        = (const float*)d_in[4];
    const float* se_w2        = (const float*)d_in[5];
    const float* se_b2        = (const float*)d_in[6];
    const float* re_w1        = (const float*)d_in[7];
    const float* re_b1        = (const float*)d_in[8];
    const float* re_w2        = (const float*)d_in[9];
    const float* re_b2        = (const float*)d_in[10];
    const float* ra_w         = (const float*)d_in[11];
    const float* ra_b         = (const float*)d_in[12];
    const float* ae_w1        = (const float*)d_in[13];
    const float* ae_b1        = (const float*)d_in[14];
    const float* ae_w2        = (const float*)d_in[15];
    const float* ae_b2        = (const float*)d_in[16];
    const float* action_embed = (const float*)d_in[17];
    const int*   action       = (const int*)d_in[19];
    const int*   agent_id     = (const int*)d_in[20];
    float* out = (float*)d_out;

    static bool attr = false;
    if (!attr) {
        cudaFuncSetAttribute(k_rel, cudaFuncAttributeMaxDynamicSharedMemorySize, SM_REL);
        cudaFuncSetAttribute(k_tail, cudaFuncAttributeMaxDynamicSharedMemorySize, SM_TAIL);
        attr = true;
    }

    k_enc_prep<<<604, 256>>>(states, se_w1, se_b1, se_w2, se_b2,
                             re_w1, re_w2, ra_w, ae_w1, ae_w2);
    k_smm<<<128, 256>>>(re_w1);
    k_rel<<<B * A, 256, SM_REL>>>(relations, alive_mask, re_b1, re_b2, agent_id);
    k_tail<<<B * 4, 512, SM_TAIL>>>(ra_w, ra_b, ae_b1, ae_b2, agent_id);
    k_final<<<B, 256>>>(action_embed, action, agent_id, out);
}

// round 15
// speedup vs baseline: 1.0016x; 1.0016x over previous
#include <cuda_runtime.h>
#include <cuda_bf16.h>
#include <cstdint>

#define B 32
#define A 64
#define SLEN 256
#define H 128
#define RLEN 64
#define E 16
#define K3 (3 * H)
#define K4 (4 * H)

__device__ float g_s1[B * A * H];
__device__ float g_Cs[B * H * A];
__device__ float g_pooled[B * A * 2 * H];
__device__ float g_ragent[B * A * 2 * H];
__device__ float g_s2[B * A * H];
__device__ float g_aeT[B * 2 * H * A];     // [b][c(256)][j(64)]
__device__ __align__(16) uint4 g_w1fh[8 * 4 * 32],   g_w1fl[8 * 4 * 32];
__device__ __align__(16) uint4 g_w2fh[16 * 8 * 32],  g_w2fl[16 * 8 * 32];
__device__ __align__(16) uint4 g_wrfh[8 * 24 * 32],  g_wrfl[8 * 24 * 32];
__device__ __align__(16) uint4 g_wa1fh[8 * 32 * 32], g_wa1fl[8 * 32 * 32];
__device__ __align__(16) uint4 g_wa2fh[16 * 8 * 32], g_wa2fl[16 * 8 * 32];

#define MMA4(d, a, b0, b1) asm volatile( \
    "mma.sync.aligned.m16n8k16.row.col.f32.bf16.bf16.f32 " \
    "{%0,%1,%2,%3},{%4,%5,%6,%7},{%8,%9},{%0,%1,%2,%3};" \
    : "+f"((d)[0]), "+f"((d)[1]), "+f"((d)[2]), "+f"((d)[3]) \
    : "r"((a)[0]), "r"((a)[1]), "r"((a)[2]), "r"((a)[3]), "r"(b0), "r"(b1))
#define LDSM4(r, a) asm volatile( \
    "ldmatrix.sync.aligned.m8n8.x4.shared.b16 {%0,%1,%2,%3}, [%4];" \
    : "=r"((r)[0]), "=r"((r)[1]), "=r"((r)[2]), "=r"((r)[3]) : "r"(a))
#define LDSM4T(r, a) asm volatile( \
    "ldmatrix.sync.aligned.m8n8.x4.trans.shared.b16 {%0,%1,%2,%3}, [%4];" \
    : "=r"((r)[0]), "=r"((r)[1]), "=r"((r)[2]), "=r"((r)[3]) : "r"(a))

__device__ __forceinline__ uint32_t s2u(const void* p) {
    uint32_t a;
    asm("{ .reg .u64 t; cvta.to.shared.u64 t, %1; cvt.u32.u64 %0, t; }" : "=r"(a) : "l"(p));
    return a;
}
__device__ __forceinline__ uint32_t pkhi(float a, float b) {
    __nv_bfloat162 t = __halves2bfloat162(__float2bfloat16(a), __float2bfloat16(b));
    return *reinterpret_cast<uint32_t*>(&t);
}
__device__ __forceinline__ uint32_t pklo(float a, float b) {
    float ra = a - __bfloat162float(__float2bfloat16(a));
    float rb = b - __bfloat162float(__float2bfloat16(b));
    __nv_bfloat162 t = __halves2bfloat162(__float2bfloat16(ra), __float2bfloat16(rb));
    return *reinterpret_cast<uint32_t*>(&t);
}
__device__ __forceinline__ void pack_frag(const float* W, int N, int r0, int ka,
                                          uint4* dh, uint4* dl) {
    float v00 = W[ka * N + r0],       v01 = W[(ka + 1) * N + r0];
    float v10 = W[ka * N + r0 + 8],   v11 = W[(ka + 1) * N + r0 + 8];
    float v20 = W[(ka + 8) * N + r0], v21 = W[(ka + 9) * N + r0];
    float v30 = W[(ka + 8) * N + r0 + 8], v31 = W[(ka + 9) * N + r0 + 8];
    *dh = make_uint4(pkhi(v00, v01), pkhi(v10, v11), pkhi(v20, v21), pkhi(v30, v31));
    *dl = make_uint4(pklo(v00, v01), pklo(v10, v11), pklo(v20, v21), pklo(v30, v31));
}

// ---------------- k_enc_prep ----------------
__global__ __launch_bounds__(256) void k_enc_prep(
    const float* __restrict__ st, const float* __restrict__ w1, const float* __restrict__ b1,
    const float* __restrict__ w2, const float* __restrict__ b2,
    const float* __restrict__ rw1, const float* __restrict__ rw2,
    const float* __restrict__ raw, const float* __restrict__ aw1, const float* __restrict__ aw2)
{
    __shared__ float X[4 * SLEN];
    __shared__ float HD[4 * H];
    __shared__ float RED[2 * 4 * H];
    const int t = threadIdx.x;

    if (blockIdx.x >= 512) {
        int it = (blockIdx.x - 512) * 256 + t;
        if (it < 1024) {
            const int i = it, lane = i & 31, ks = (i >> 5) & 3, slot = i >> 7;
            pack_frag(rw1, 128, slot * 16 + (lane >> 2), ks * 16 + 2 * (lane & 3),
                      &g_w1fh[i], &g_w1fl[i]);
        } else if (it < 5120) {
            const int i = it - 1024, lane = i & 31, ks = (i >> 5) & 7, slot = i >> 8;
            pack_frag(rw2, 256, slot * 16 + (lane >> 2), ks * 16 + 2 * (lane & 3),
                      &g_w2fh[i], &g_w2fl[i]);
        } else if (it < 11264) {
            const int i = it - 5120, lane = i & 31, ks = (i >> 5) % 24, slot = i / 768;
            pack_frag(raw, 128, slot * 16 + (lane >> 2), ks * 16 + 2 * (lane & 3),
                      &g_wrfh[i], &g_wrfl[i]);
        } else if (it < 19456) {
            const int i = it - 11264, lane = i & 31, ks = (i >> 5) & 31, slot = i >> 10;
            pack_frag(aw1, 128, slot * 16 + (lane >> 2), ks * 16 + 2 * (lane & 3),
                      &g_wa1fh[i], &g_wa1fl[i]);
        } else {
            const int i = it - 19456, lane = i & 31, ks = (i >> 5) & 7, slot = i >> 8;
            pack_frag(aw2, 256, slot * 16 + (lane >> 2), ks * 16 + 2 * (lane & 3),
                      &g_wa2fh[i], &g_wa2fl[i]);
        }
        return;
    }

    const int row0 = blockIdx.x * 4;
    for (int i = t; i < 4 * SLEN; i += 256) X[i] = st[(size_t)row0 * SLEN + i];
    __syncthreads();
    const int h = t & 127, kh = t >> 7;
    {
        float acc[4] = {0.f, 0.f, 0.f, 0.f};
        const float4* X4 = (const float4*)X;
        const int k0 = kh * 128;
#pragma unroll 4
        for (int k = k0; k < k0 + 128; k += 4) {
            float w0 = w1[k * H + h], wA = w1[(k + 1) * H + h], wB = w1[(k + 2) * H + h], wC = w1[(k + 3) * H + h];
#pragma unroll
            for (int j = 0; j < 4; j++) {
                float4 x = X4[j * (SLEN / 4) + (k >> 2)];
                acc[j] = fmaf(x.x, w0, acc[j]); acc[j] = fmaf(x.y, wA, acc[j]);
                acc[j] = fmaf(x.z, wB, acc[j]); acc[j] = fmaf(x.w, wC, acc[j]);
            }
        }
#pragma unroll
        for (int j = 0; j < 4; j++) RED[(kh * 4 + j) * H + h] = acc[j];
    }
    __syncthreads();
    for (int idx = t; idx < 4 * H; idx += 256)
        HD[idx] = fmaxf(RED[idx] + RED[4 * H + idx] + b1[idx & 127], 0.f);
    __syncthreads();
    {
        const int rb = kh * 2;
        float acc[2];
        const float bb = b2[h];
        acc[0] = bb; acc[1] = bb;
        const float4* H4 = (const float4*)HD;
#pragma unroll 4
        for (int k = 0; k < H; k += 4) {
            float w0 = w2[k * H + h], wA = w2[(k + 1) * H + h], wB = w2[(k + 2) * H + h], wC = w2[(k + 3) * H + h];
#pragma unroll
            for (int j = 0; j < 2; j++) {
                float4 x = H4[(rb + j) * (H / 4) + (k >> 2)];
                acc[j] = fmaf(x.x, w0, acc[j]); acc[j] = fmaf(x.y, wA, acc[j]);
                acc[j] = fmaf(x.z, wB, acc[j]); acc[j] = fmaf(x.w, wC, acc[j]);
            }
        }
#pragma unroll
        for (int j = 0; j < 2; j++) g_s1[(size_t)(row0 + rb + j) * H + h] = fmaxf(acc[j], 0.f);
    }
}

// ---------------- k_smm ----------------
__global__ __launch_bounds__(256) void k_smm(const float* __restrict__ w1)
{
    __shared__ float S[16 * 128];
    const int b = blockIdx.x >> 2, j0 = (blockIdx.x & 3) * 16, t = threadIdx.x;
    for (int i = t; i < 16 * 128; i += 256)
        S[i] = g_s1[(size_t)b * 8192 + (size_t)j0 * 128 + i];
    __syncthreads();
    const int c = t & 127, jh = t >> 7;
    float acc[8];
#pragma unroll
    for (int j = 0; j < 8; j++) acc[j] = 0.f;
    const float4* S4 = (const float4*)S;
#pragma unroll 2
    for (int k4 = 0; k4 < 32; k4++) {
        const int k = 4 * k4;
        float w0 = w1[(64 + k) * 128 + c], wA = w1[(65 + k) * 128 + c];
        float wB = w1[(66 + k) * 128 + c], wC = w1[(67 + k) * 128 + c];
#pragma unroll
        for (int j = 0; j < 8; j++) {
            float4 s = S4[(jh * 8 + j) * 32 + k4];
            acc[j] = fmaf(s.x, w0, acc[j]); acc[j] = fmaf(s.y, wA, acc[j]);
            acc[j] = fmaf(s.z, wB, acc[j]); acc[j] = fmaf(s.w, wC, acc[j]);
        }
    }
#pragma unroll
    for (int j = 0; j < 8; j++)
        g_Cs[(size_t)b * 8192 + c * 64 + j0 + jh * 8 + j] = acc[j];
}

// ---------------- k_rel: round-robin accumulator MMA order ----------------
#define XS 72
#define HTS 72
#define SM_REL 55552

// interleaved: term-k for both accs before term-k+1 (breaks RAW chains)
#define DO6(q, BH, BL) \
    MMA4(ac[q], ah, BH[0], BH[1]);     MMA4(ac[q + 1], ah, BH[2], BH[3]); \
    MMA4(ac[q], ah, BL[0], BL[1]);     MMA4(ac[q + 1], ah, BL[2], BL[3]); \
    MMA4(ac[q], alr, BH[0], BH[1]);    MMA4(ac[q + 1], alr, BH[2], BH[3]);

#define DO12(q, BH, BL) \
    MMA4(acM[q], aha, BH[0], BH[1]);   MMA4(acX[q], ahb, BH[0], BH[1]); \
    MMA4(acM[q + 1], aha, BH[2], BH[3]); MMA4(acX[q + 1], ahb, BH[2], BH[3]); \
    MMA4(acM[q], aha, BL[0], BL[1]);   MMA4(acX[q], ahb, BL[0], BL[1]); \
    MMA4(acM[q + 1], aha, BL[2], BL[3]); MMA4(acX[q + 1], ahb, BL[2], BL[3]); \
    MMA4(acM[q], ala, BH[0], BH[1]);   MMA4(acX[q], alb, BH[0], BH[1]); \
    MMA4(acM[q + 1], ala, BH[2], BH[3]); MMA4(acX[q + 1], alb, BH[2], BH[3]);

__global__ __launch_bounds__(256, 2) void k_rel(
    const float* __restrict__ rel, const float* __restrict__ alive,
    const float* __restrict__ b1, const float* __restrict__ b2,
    const int* __restrict__ agp)
{
    extern __shared__ unsigned char smem[];
    __nv_bfloat16* XH = (__nv_bfloat16*)smem;
    __nv_bfloat16* XL = (__nv_bfloat16*)(smem + 9216);
    __nv_bfloat16* HTh = (__nv_bfloat16*)(smem + 18432);
    __nv_bfloat16* HTl = (__nv_bfloat16*)(smem + 36864);
    float* sal = (float*)(smem + 55296);

    const int tid = threadIdx.x, w = tid >> 5, l = tid & 31, g = l >> 2, t4 = l & 3;
    const int bi = blockIdx.x, b = bi >> 6, i = bi & 63;
    if (tid < 64) sal[tid] = alive[b * 64 + tid];

    const int sel = l >> 3, lr = l & 7;
    const uint32_t xrow = (uint32_t)(((lr + ((sel >> 1) << 3)) * XS + ((sel & 1) << 3)) * 2);
    const uint32_t hrow = (uint32_t)(((lr + ((sel & 1) << 3)) * HTS + ((sel >> 1) << 3)) * 2);
    const uint32_t xh_b = s2u(XH), xl_b = s2u(XL), hh_b = s2u(HTh), hl_b = s2u(HTl);

    {
        const float4* rr4 = (const float4*)(rel + (size_t)bi * 4096);
        for (int idx = tid; idx < 1024; idx += 256) {
            const int j = idx >> 4, k4 = idx & 15;
            float4 v = rr4[idx];
            *(uint2*)(XH + j * XS + k4 * 4) = make_uint2(pkhi(v.x, v.y), pkhi(v.z, v.w));
            *(uint2*)(XL + j * XS + k4 * 4) = make_uint2(pklo(v.x, v.y), pklo(v.z, v.w));
        }
    }
    const int r0 = w * 16 + g;
    float2 csA[8], csB[8];
    {
        const float* pA = g_Cs + (size_t)b * 8192 + r0 * 64;
        const float* pB = pA + 8 * 64;
#pragma unroll
        for (int n = 0; n < 8; n++) {
            csA[n] = *(const float2*)(pA + n * 8 + 2 * t4);
            csB[n] = *(const float2*)(pB + n * 8 + 2 * t4);
        }
    }
    __syncthreads();

    float ac[8][4];
#pragma unroll
    for (int n = 0; n < 8; n++) { ac[n][0] = 0.f; ac[n][1] = 0.f; ac[n][2] = 0.f; ac[n][3] = 0.f; }
#pragma unroll
    for (int ks = 0; ks < 4; ks++) {
        const uint4 AH = g_w1fh[(w * 4 + ks) * 32 + l];
        const uint4 AL = g_w1fl[(w * 4 + ks) * 32 + l];
        const uint32_t ah[4] = {AH.x, AH.y, AH.z, AH.w};
        const uint32_t alr[4] = {AL.x, AL.y, AL.z, AL.w};
        const uint32_t kb = (uint32_t)(ks * 32);
        uint32_t bh0[4], bl0[4], bh1[4], bl1[4];
        LDSM4(bh0, xh_b + kb + xrow);
        LDSM4(bl0, xl_b + kb + xrow);
        LDSM4(bh1, xh_b + (uint32_t)(16 * XS * 2) + kb + xrow);
        LDSM4(bl1, xl_b + (uint32_t)(16 * XS * 2) + kb + xrow);
        DO6(0, bh0, bl0)
        DO6(2, bh1, bl1)
        LDSM4(bh0, xh_b + (uint32_t)(32 * XS * 2) + kb + xrow);
        LDSM4(bl0, xl_b + (uint32_t)(32 * XS * 2) + kb + xrow);
        LDSM4(bh1, xh_b + (uint32_t)(48 * XS * 2) + kb + xrow);
        LDSM4(bl1, xl_b + (uint32_t)(48 * XS * 2) + kb + xrow);
        DO6(4, bh0, bl0)
        DO6(6, bh1, bl1)
    }
    {
        const float bA = b1[r0], bB = b1[r0 + 8];
#pragma unroll
        for (int n = 0; n < 8; n++) {
            const int j0 = n * 8 + 2 * t4;
            float v0 = fmaxf(ac[n][0] + csA[n].x + bA, 0.f);
            float v1 = fmaxf(ac[n][1] + csA[n].y + bA, 0.f);
            float v2 = fmaxf(ac[n][2] + csB[n].x + bB, 0.f);
            float v3 = fmaxf(ac[n][3] + csB[n].y + bB, 0.f);
            *(uint32_t*)(HTh + r0 * HTS + j0) = pkhi(v0, v1);
            *(uint32_t*)(HTl + r0 * HTS + j0) = pklo(v0, v1);
            *(uint32_t*)(HTh + (r0 + 8) * HTS + j0) = pkhi(v2, v3);
            *(uint32_t*)(HTl + (r0 + 8) * HTS + j0) = pklo(v2, v3);
        }
    }
    __syncthreads();

    float acM[8][4], acX[8][4];
#pragma unroll
    for (int n = 0; n < 8; n++) {
        acM[n][0] = 0.f; acM[n][1] = 0.f; acM[n][2] = 0.f; acM[n][3] = 0.f;
        acX[n][0] = 0.f; acX[n][1] = 0.f; acX[n][2] = 0.f; acX[n][3] = 0.f;
    }
#pragma unroll 1
    for (int ks = 0; ks < 8; ks++) {
        const uint4 AHa = g_w2fh[(w * 8 + ks) * 32 + l];
        const uint4 ALa = g_w2fl[(w * 8 + ks) * 32 + l];
        const uint4 AHb = g_w2fh[((8 + w) * 8 + ks) * 32 + l];
        const uint4 ALb = g_w2fl[((8 + w) * 8 + ks) * 32 + l];
        const uint32_t aha[4] = {AHa.x, AHa.y, AHa.z, AHa.w};
        const uint32_t ala[4] = {ALa.x, ALa.y, ALa.z, ALa.w};
        const uint32_t ahb[4] = {AHb.x, AHb.y, AHb.z, AHb.w};
        const uint32_t alb[4] = {ALb.x, ALb.y, ALb.z, ALb.w};
        const uint32_t kb = (uint32_t)(ks * 16 * HTS * 2);
        uint32_t bh0[4], bl0[4], bh1[4], bl1[4];
        LDSM4T(bh0, hh_b + kb + hrow);
        LDSM4T(bl0, hl_b + kb + hrow);
        LDSM4T(bh1, hh_b + kb + 32 + hrow);
        LDSM4T(bl1, hl_b + kb + 32 + hrow);
        DO12(0, bh0, bl0)
        DO12(2, bh1, bl1)
        LDSM4T(bh0, hh_b + kb + 64 + hrow);
        LDSM4T(bl0, hl_b + kb + 64 + hrow);
        LDSM4T(bh1, hh_b + kb + 96 + hrow);
        LDSM4T(bl1, hl_b + kb + 96 + hrow);
        DO12(4, bh0, bl0)
        DO12(6, bh1, bl1)
    }
    {
        const int rrA = w * 16 + g;
        const int rrB = 128 + w * 16 + g;
        const int gag = *agp;
        const bool isag = (i == gag);
        const float bMA = b2[rrA], bMB = b2[rrA + 8];
        const float bXA = b2[rrB], bXB = b2[rrB + 8];
        float s0 = 0.f, s1 = 0.f, t0 = 0.f, t1 = 0.f;
        float* rg = g_ragent + (size_t)(b * 64) * 256;
#pragma unroll
        for (int n = 0; n < 8; n++) {
            const int j0 = n * 8 + 2 * t4;
            const float al0 = sal[j0], al1 = sal[j0 + 1];
            float m0 = fmaxf(acM[n][0] + bMA, 0.f), m1 = fmaxf(acM[n][1] + bMA, 0.f);
            float m2 = fmaxf(acM[n][2] + bMB, 0.f), m3 = fmaxf(acM[n][3] + bMB, 0.f);
            float x0 = fmaxf(acX[n][0] + bXA, 0.f), x1 = fmaxf(acX[n][1] + bXA, 0.f);
            float x2 = fmaxf(acX[n][2] + bXB, 0.f), x3 = fmaxf(acX[n][3] + bXB, 0.f);
            if (isag) {
                rg[(size_t)j0 * 256 + rrA] = m0;
                rg[(size_t)(j0 + 1) * 256 + rrA] = m1;
                rg[(size_t)j0 * 256 + rrA + 8] = m2;
                rg[(size_t)(j0 + 1) * 256 + rrA + 8] = m3;
                rg[(size_t)j0 * 256 + rrB] = x0;
                rg[(size_t)(j0 + 1) * 256 + rrB] = x1;
                rg[(size_t)j0 * 256 + rrB + 8] = x2;
                rg[(size_t)(j0 + 1) * 256 + rrB + 8] = x3;
            }
            s0 += m0 * al0 + m1 * al1;
            s1 += m2 * al0 + m3 * al1;
            t0 = fmaxf(t0, fmaxf(x0 * al0, x1 * al1));
            t1 = fmaxf(t1, fmaxf(x2 * al0, x3 * al1));
        }
        s0 += __shfl_xor_sync(0xffffffffu, s0, 1); s0 += __shfl_xor_sync(0xffffffffu, s0, 2);
        s1 += __shfl_xor_sync(0xffffffffu, s1, 1); s1 += __shfl_xor_sync(0xffffffffu, s1, 2);
        t0 = fmaxf(t0, __shfl_xor_sync(0xffffffffu, t0, 1)); t0 = fmaxf(t0, __shfl_xor_sync(0xffffffffu, t0, 2));
        t1 = fmaxf(t1, __shfl_xor_sync(0xffffffffu, t1, 1)); t1 = fmaxf(t1, __shfl_xor_sync(0xffffffffu, t1, 2));
        if (t4 == 0) {
            g_pooled[(size_t)bi * 256 + rrA] = s0 * (1.f / 64.f);
            g_pooled[(size_t)bi * 256 + rrA + 8] = s1 * (1.f / 64.f);
            g_pooled[(size_t)bi * 256 + rrB] = t0;
            g_pooled[(size_t)bi * 256 + rrB + 8] = t1;
        }
    }
}

// ---------------- k_tail: 512 thr, split-K warp pairs, prefetch, RR MMA order ----------------
#define XT 520
#define S2S 132
#define HT2 24
#define SM_TAIL 88848

__global__ __launch_bounds__(512, 1) void k_tail(
    const float* __restrict__ raw, const float* __restrict__ rab,
    const float* __restrict__ ab1, const float* __restrict__ ab2,
    const int* __restrict__ agp)
{
    extern __shared__ unsigned char smem[];
    __nv_bfloat16* XH = (__nv_bfloat16*)smem;
    __nv_bfloat16* XL = (__nv_bfloat16*)(smem + 16640);
    float* S2f = (float*)(smem + 33280);
    __nv_bfloat16* HTh = (__nv_bfloat16*)(smem + 42256);
    __nv_bfloat16* HTl = (__nv_bfloat16*)(smem + 48400);
    float* RED = (float*)(smem + 54544);
    float* AG = (float*)(smem + 87312);

    const int tid = threadIdx.x, w = tid >> 5, l = tid & 31, g = l >> 2, t4 = l & 3;
    const int wp = w & 7, kh2 = w >> 3;
    const int b = blockIdx.x >> 2, jg0 = (blockIdx.x & 3) * 16;
    const int gag = *agp;
    const int sel = l >> 3, lr = l & 7;
    const uint32_t xrow = (uint32_t)(((lr + ((sel >> 1) << 3)) * XT + ((sel & 1) << 3)) * 2);
    const uint32_t hrow = (uint32_t)(((lr + ((sel & 1) << 3)) * HT2 + ((sel >> 1) << 3)) * 2);
    const uint32_t xh_b = s2u(XH), xl_b = s2u(XL), hh_b = s2u(HTh), hl_b = s2u(HTl);
    const int r0 = wp * 16 + g;
    const int j0 = 2 * t4, j1 = 8 + 2 * t4;

    for (int idx = tid; idx < 16 * 32; idx += 512) {
        const int j = idx >> 5, k4 = idx & 31;
        float4 v = *(const float4*)(g_s1 + (size_t)(b * 64 + jg0 + j) * 128 + k4 * 4);
        *(uint2*)(XH + j * XT + k4 * 4) = make_uint2(pkhi(v.x, v.y), pkhi(v.z, v.w));
        *(uint2*)(XL + j * XT + k4 * 4) = make_uint2(pklo(v.x, v.y), pklo(v.z, v.w));
    }
    for (int idx = tid; idx < 16 * 64; idx += 512) {
        const int j = idx >> 6, k4 = idx & 63;
        float4 v = *(const float4*)(g_pooled + (size_t)(b * 64 + j + jg0) * 256 + k4 * 4);
        *(uint2*)(XH + j * XT + 128 + k4 * 4) = make_uint2(pkhi(v.x, v.y), pkhi(v.z, v.w));
        *(uint2*)(XL + j * XT + 128 + k4 * 4) = make_uint2(pklo(v.x, v.y), pklo(v.z, v.w));
    }
    if (tid < 96) {
        float4 v = (tid < 32)
            ? *(const float4*)(g_s1 + (size_t)(b * 64 + gag) * 128 + tid * 4)
            : *(const float4*)(g_pooled + (size_t)(b * 64 + gag) * 256 + (tid - 32) * 4);
        *(float4*)(AG + tid * 4) = v;
    }
    __syncthreads();

    // ---- ra GEMM: K=384, 12 ks per warp-half, prefetched, RR order ----
    {
        float a0[4] = {0.f, 0.f, 0.f, 0.f}, a1[4] = {0.f, 0.f, 0.f, 0.f};
        const int ks0 = kh2 * 12;
        uint4 AH = g_wrfh[(wp * 24 + ks0) * 32 + l];
        uint4 AL = g_wrfl[(wp * 24 + ks0) * 32 + l];
#pragma unroll 1
        for (int ks = ks0; ks < ks0 + 12; ks++) {
            uint4 AHn = AH, ALn = AL;
            if (ks + 1 < ks0 + 12) {
                AHn = g_wrfh[(wp * 24 + ks + 1) * 32 + l];
                ALn = g_wrfl[(wp * 24 + ks + 1) * 32 + l];
            }
            const uint32_t ah[4] = {AH.x, AH.y, AH.z, AH.w};
            const uint32_t alr[4] = {AL.x, AL.y, AL.z, AL.w};
            uint32_t bh[4], bl[4];
            LDSM4(bh, xh_b + (uint32_t)(ks * 32) + xrow);
            LDSM4(bl, xl_b + (uint32_t)(ks * 32) + xrow);
            MMA4(a0, ah, bh[0], bh[1]);  MMA4(a1, ah, bh[2], bh[3]);
            MMA4(a0, ah, bl[0], bl[1]);  MMA4(a1, ah, bl[2], bl[3]);
            MMA4(a0, alr, bh[0], bh[1]); MMA4(a1, alr, bh[2], bh[3]);
            AH = AHn; AL = ALn;
        }
        float* RP = RED + kh2 * 2048;
        RP[j0 * 128 + r0] = a0[0];       RP[(j0 + 1) * 128 + r0] = a0[1];
        RP[j0 * 128 + r0 + 8] = a0[2];   RP[(j0 + 1) * 128 + r0 + 8] = a0[3];
        RP[j1 * 128 + r0] = a1[0];       RP[(j1 + 1) * 128 + r0] = a1[1];
        RP[j1 * 128 + r0 + 8] = a1[2];   RP[(j1 + 1) * 128 + r0 + 8] = a1[3];
    }
    {
        const int h = tid & 127, kh = tid >> 7;
        float acc = 0.f;
        const int k0 = kh * 96;
#pragma unroll 4
        for (int k = k0; k < k0 + 96; k++)
            acc = fmaf(AG[k], raw[k * 128 + h], acc);
        RED[4096 + kh * 128 + h] = acc;
    }
    __syncthreads();
    for (int idx = tid; idx < 2048; idx += 512) {
        const int c = idx >> 4, j = idx & 15;
        S2f[j * S2S + c] = fmaxf(RED[j * 128 + c] + RED[2048 + j * 128 + c] + rab[c], 0.f);
    }
    if (tid < 128)
        S2f[16 * S2S + tid] = fmaxf(RED[4096 + tid] + RED[4224 + tid]
                                  + RED[4352 + tid] + RED[4480 + tid] + rab[tid], 0.f);
    __syncthreads();

    for (int idx = tid; idx < 16 * 64; idx += 512) {
        const int j = idx >> 6, k4 = idx & 63;
        float4 v = *(const float4*)(g_ragent + (size_t)(b * 64 + jg0 + j) * 256 + k4 * 4);
        *(uint2*)(XH + j * XT + k4 * 4) = make_uint2(pkhi(v.x, v.y), pkhi(v.z, v.w));
        *(uint2*)(XL + j * XT + k4 * 4) = make_uint2(pklo(v.x, v.y), pklo(v.z, v.w));
    }
    for (int idx = tid; idx < 16 * 32; idx += 512) {
        const int j = idx >> 5, k4 = idx & 31;
        float4 v = *(const float4*)(S2f + j * S2S + k4 * 4);
        *(uint2*)(XH + j * XT + 256 + k4 * 4) = make_uint2(pkhi(v.x, v.y), pkhi(v.z, v.w));
        *(uint2*)(XL + j * XT + 256 + k4 * 4) = make_uint2(pklo(v.x, v.y), pklo(v.z, v.w));
        *(float4*)(g_s2 + (size_t)(b * 64 + jg0 + j) * 128 + k4 * 4) = v;
        float4 va = *(const float4*)(S2f + 16 * S2S + k4 * 4);
        *(uint2*)(XH + j * XT + 384 + k4 * 4) = make_uint2(pkhi(va.x, va.y), pkhi(va.z, va.w));
        *(uint2*)(XL + j * XT + 384 + k4 * 4) = make_uint2(pklo(va.x, va.y), pklo(va.z, va.w));
    }
    __syncthreads();

    // ---- ae layer 1: K=512, 16 ks per warp-half, prefetched, RR order ----
    {
        float a0[4] = {0.f, 0.f, 0.f, 0.f}, a1[4] = {0.f, 0.f, 0.f, 0.f};
        const int ks0 = kh2 * 16;
        uint4 AH = g_wa1fh[(wp * 32 + ks0) * 32 + l];
        uint4 AL = g_wa1fl[(wp * 32 + ks0) * 32 + l];
#pragma unroll 1
        for (int ks = ks0; ks < ks0 + 16; ks++) {
            uint4 AHn = AH, ALn = AL;
            if (ks + 1 < ks0 + 16) {
                AHn = g_wa1fh[(wp * 32 + ks + 1) * 32 + l];
                ALn = g_wa1fl[(wp * 32 + ks + 1) * 32 + l];
            }
            const uint32_t ah[4] = {AH.x, AH.y, AH.z, AH.w};
            const uint32_t alr[4] = {AL.x, AL.y, AL.z, AL.w};
            uint32_t bh[4], bl[4];
            LDSM4(bh, xh_b + (uint32_t)(ks * 32) + xrow);
            LDSM4(bl, xl_b + (uint32_t)(ks * 32) + xrow);
            MMA4(a0, ah, bh[0], bh[1]);  MMA4(a1, ah, bh[2], bh[3]);
            MMA4(a0, ah, bl[0], bl[1]);  MMA4(a1, ah, bl[2], bl[3]);
            MMA4(a0, alr, bh[0], bh[1]); MMA4(a1, alr, bh[2], bh[3]);
            AH = AHn; AL = ALn;
        }
        float* RP = RED + kh2 * 2048;
        RP[j0 * 128 + r0] = a0[0];       RP[(j0 + 1) * 128 + r0] = a0[1];
        RP[j0 * 128 + r0 + 8] = a0[2];   RP[(j0 + 1) * 128 + r0 + 8] = a0[3];
        RP[j1 * 128 + r0] = a1[0];       RP[(j1 + 1) * 128 + r0] = a1[1];
        RP[j1 * 128 + r0 + 8] = a1[2];   RP[(j1 + 1) * 128 + r0 + 8] = a1[3];
    }
    __syncthreads();
    for (int idx = tid; idx < 2048; idx += 512) {
        const int c = idx >> 4, j = idx & 15;
        float v = fmaxf(RED[j * 128 + c] + RED[2048 + j * 128 + c] + ab1[c], 0.f);
        __nv_bfloat16 hh = __float2bfloat16(v);
        HTh[c * HT2 + j] = hh;
        HTl[c * HT2 + j] = __float2bfloat16(v - __bfloat162float(hh));
    }
    __syncthreads();

    // ---- ae layer 2: K=128, 4 ks per warp-half, prefetched, RR order ----
    {
        float acM0[4] = {0.f, 0.f, 0.f, 0.f}, acM1[4] = {0.f, 0.f, 0.f, 0.f};
        float acX0[4] = {0.f, 0.f, 0.f, 0.f}, acX1[4] = {0.f, 0.f, 0.f, 0.f};
        const int ks0 = kh2 * 4;
        uint4 AHa = g_wa2fh[(wp * 8 + ks0) * 32 + l];
        uint4 ALa = g_wa2fl[(wp * 8 + ks0) * 32 + l];
        uint4 AHb = g_wa2fh[((8 + wp) * 8 + ks0) * 32 + l];
        uint4 ALb = g_wa2fl[((8 + wp) * 8 + ks0) * 32 + l];
#pragma unroll 1
        for (int ks = ks0; ks < ks0 + 4; ks++) {
            uint4 AHan = AHa, ALan = ALa, AHbn = AHb, ALbn = ALb;
            if (ks + 1 < ks0 + 4) {
                AHan = g_wa2fh[(wp * 8 + ks + 1) * 32 + l];
                ALan = g_wa2fl[(wp * 8 + ks + 1) * 32 + l];
                AHbn = g_wa2fh[((8 + wp) * 8 + ks + 1) * 32 + l];
                ALbn = g_wa2fl[((8 + wp) * 8 + ks + 1) * 32 + l];
            }
            const uint32_t aha[4] = {AHa.x, AHa.y, AHa.z, AHa.w};
            const uint32_t ala[4] = {ALa.x, ALa.y, ALa.z, ALa.w};
            const uint32_t ahb[4] = {AHb.x, AHb.y, AHb.z, AHb.w};
            const uint32_t alb[4] = {ALb.x, ALb.y, ALb.z, ALb.w};
            uint32_t bh[4], bl[4];
            LDSM4T(bh, hh_b + (uint32_t)(ks * 16 * HT2 * 2) + hrow);
            LDSM4T(bl, hl_b + (uint32_t)(ks * 16 * HT2 * 2) + hrow);
            MMA4(acM0, aha, bh[0], bh[1]);  MMA4(acX0, ahb, bh[0], bh[1]);
            MMA4(acM1, aha, bh[2], bh[3]);  MMA4(acX1, ahb, bh[2], bh[3]);
            MMA4(acM0, aha, bl[0], bl[1]);  MMA4(acX0, ahb, bl[0], bl[1]);
            MMA4(acM1, aha, bl[2], bl[3]);  MMA4(acX1, ahb, bl[2], bl[3]);
            MMA4(acM0, ala, bh[0], bh[1]);  MMA4(acX0, alb, bh[0], bh[1]);
            MMA4(acM1, ala, bh[2], bh[3]);  MMA4(acX1, alb, bh[2], bh[3]);
            AHa = AHan; ALa = ALan; AHb = AHbn; ALb = ALbn;
        }
        float* RP = RED + kh2 * 4096;
        RP[j0 * 256 + r0] = acM0[0];         RP[(j0 + 1) * 256 + r0] = acM0[1];
        RP[j0 * 256 + r0 + 8] = acM0[2];     RP[(j0 + 1) * 256 + r0 + 8] = acM0[3];
        RP[j1 * 256 + r0] = acM1[0];         RP[(j1 + 1) * 256 + r0] = acM1[1];
        RP[j1 * 256 + r0 + 8] = acM1[2];     RP[(j1 + 1) * 256 + r0 + 8] = acM1[3];
        RP[j0 * 256 + 128 + r0] = acX0[0];   RP[(j0 + 1) * 256 + 128 + r0] = acX0[1];
        RP[j0 * 256 + 128 + r0 + 8] = acX0[2]; RP[(j0 + 1) * 256 + 128 + r0 + 8] = acX0[3];
        RP[j1 * 256 + 128 + r0] = acX1[0];   RP[(j1 + 1) * 256 + 128 + r0] = acX1[1];
        RP[j1 * 256 + 128 + r0 + 8] = acX1[2]; RP[(j1 + 1) * 256 + 128 + r0 + 8] = acX1[3];
    }
    __syncthreads();
    {
        float* ae = g_aeT + (size_t)b * 256 * 64 + jg0;
        for (int idx = tid; idx < 4096; idx += 512) {
            const int c = idx >> 4, j = idx & 15;
            float v = fmaxf(RED[j * 256 + c] + RED[4096 + j * 256 + c] + ab2[c], 0.f);
            ae[c * 64 + j] = v;
        }
    }
}

// ---------------- k_final (g_aeT layout) ----------------
__global__ __launch_bounds__(256) void k_final(
    const float* __restrict__ action_embed, const int* __restrict__ action,
    const int* __restrict__ agp, float* __restrict__ out)
{
    const int b = blockIdx.x, t = threadIdx.x;
    const int h = t & 127, jp = t >> 7;
    const int a = action[b], g = *agp;
    const float sel = (a < E) ? action_embed[a * H + h]
                              : g_aeT[((size_t)b * 256 + h) * 64 + (a - E)];
    float* out_state = out;
    float* out_sel = out + (size_t)B * A * H;
    float* out_ps = out_sel + (size_t)B * H;
    if (jp == 0) out_sel[b * H + h] = sel;
    for (int j = jp; j < A; j += 2) {
        float st = g_s2[((size_t)b * A + j) * H + h];
        float ps = 0.f;
        if (a == E + j) ps = g_aeT[((size_t)b * 256 + H + h) * 64 + j];
        if (j == g) st += sel;
        out_ps[((size_t)b * A + j) * H + h] = ps;
        out_state[((size_t)b * A + j) * H + h] = st + ps;
    }
}

// ---------------- launcher ----------------
extern "C" void kernel_launch(void* const* d_in, const int* in_sizes, int n_in,
                              void* d_out, int out_size)
{
    const float* states       = (const float*)d_in[0];
    const float* relations    = (const float*)d_in[1];
    const float* alive_mask   = (const float*)d_in[2];
    const float* se_w1        = (const float*)d_in[3];
    const float* se_b1        = (const float*)d_in[4];
    const float* se_w2        = (const float*)d_in[5];
    const float* se_b2        = (const float*)d_in[6];
    const float* re_w1        = (const float*)d_in[7];
    const float* re_b1        = (const float*)d_in[8];
    const float* re_w2        = (const float*)d_in[9];
    const float* re_b2        = (const float*)d_in[10];
    const float* ra_w         = (const float*)d_in[11];
    const float* ra_b         = (const float*)d_in[12];
    const float* ae_w1        = (const float*)d_in[13];
    const float* ae_b1        = (const float*)d_in[14];
    const float* ae_w2        = (const float*)d_in[15];
    const float* ae_b2        = (const float*)d_in[16];
    const float* action_embed = (const float*)d_in[17];
    const int*   action       = (const int*)d_in[19];
    const int*   agent_id     = (const int*)d_in[20];
    float* out = (float*)d_out;

    static bool attr = false;
    if (!attr) {
        cudaFuncSetAttribute(k_rel, cudaFuncAttributeMaxDynamicSharedMemorySize, SM_REL);
        cudaFuncSetAttribute(k_tail, cudaFuncAttributeMaxDynamicSharedMemorySize, SM_TAIL);
        attr = true;
    }

    k_enc_prep<<<604, 256>>>(states, se_w1, se_b1, se_w2, se_b2,
                             re_w1, re_w2, ra_w, ae_w1, ae_w2);
    k_smm<<<128, 256>>>(re_w1);
    k_rel<<<B * A, 256, SM_REL>>>(relations, alive_mask, re_b1, re_b2, agent_id);
    k_tail<<<B * 4, 512, SM_TAIL>>>(ra_w, ra_b, ae_b1, ae_b2, agent_id);
    k_final<<<B, 256>>>(action_embed, action, agent_id, out);
}

// round 16
// speedup vs baseline: 1.0043x; 1.0027x over previous
#include <cuda_runtime.h>
#include <cuda_bf16.h>
#include <cstdint>

#define B 32
#define A 64
#define SLEN 256
#define H 128
#define RLEN 64
#define E 16
#define K3 (3 * H)
#define K4 (4 * H)

__device__ float g_s1[B * A * H];
__device__ float g_Cs[B * H * A];
__device__ float g_pooled[B * A * 2 * H];
__device__ float g_ragent[B * A * 2 * H];
__device__ float g_s2[B * A * H];
__device__ float g_aeT[B * 2 * H * A];     // [b][c(256)][j(64)]
__device__ __align__(16) uint4 g_w1fh[8 * 4 * 32],   g_w1fl[8 * 4 * 32];
__device__ __align__(16) uint4 g_w2fh[16 * 8 * 32],  g_w2fl[16 * 8 * 32];
__device__ __align__(16) uint4 g_wrfh[8 * 24 * 32],  g_wrfl[8 * 24 * 32];
__device__ __align__(16) uint4 g_wa1fh[8 * 32 * 32], g_wa1fl[8 * 32 * 32];
__device__ __align__(16) uint4 g_wa2fh[16 * 8 * 32], g_wa2fl[16 * 8 * 32];

#define MMA4(d, a, b0, b1) asm volatile( \
    "mma.sync.aligned.m16n8k16.row.col.f32.bf16.bf16.f32 " \
    "{%0,%1,%2,%3},{%4,%5,%6,%7},{%8,%9},{%0,%1,%2,%3};" \
    : "+f"((d)[0]), "+f"((d)[1]), "+f"((d)[2]), "+f"((d)[3]) \
    : "r"((a)[0]), "r"((a)[1]), "r"((a)[2]), "r"((a)[3]), "r"(b0), "r"(b1))
#define LDSM4(r, a) asm volatile( \
    "ldmatrix.sync.aligned.m8n8.x4.shared.b16 {%0,%1,%2,%3}, [%4];" \
    : "=r"((r)[0]), "=r"((r)[1]), "=r"((r)[2]), "=r"((r)[3]) : "r"(a))
#define LDSM4T(r, a) asm volatile( \
    "ldmatrix.sync.aligned.m8n8.x4.trans.shared.b16 {%0,%1,%2,%3}, [%4];" \
    : "=r"((r)[0]), "=r"((r)[1]), "=r"((r)[2]), "=r"((r)[3]) : "r"(a))

__device__ __forceinline__ uint32_t s2u(const void* p) {
    uint32_t a;
    asm("{ .reg .u64 t; cvta.to.shared.u64 t, %1; cvt.u32.u64 %0, t; }" : "=r"(a) : "l"(p));
    return a;
}
__device__ __forceinline__ uint32_t pkhi(float a, float b) {
    __nv_bfloat162 t = __halves2bfloat162(__float2bfloat16(a), __float2bfloat16(b));
    return *reinterpret_cast<uint32_t*>(&t);
}
__device__ __forceinline__ uint32_t pklo(float a, float b) {
    float ra = a - __bfloat162float(__float2bfloat16(a));
    float rb = b - __bfloat162float(__float2bfloat16(b));
    __nv_bfloat162 t = __halves2bfloat162(__float2bfloat16(ra), __float2bfloat16(rb));
    return *reinterpret_cast<uint32_t*>(&t);
}
__device__ __forceinline__ void pack_frag(const float* W, int N, int r0, int ka,
                                          uint4* dh, uint4* dl) {
    float v00 = W[ka * N + r0],       v01 = W[(ka + 1) * N + r0];
    float v10 = W[ka * N + r0 + 8],   v11 = W[(ka + 1) * N + r0 + 8];
    float v20 = W[(ka + 8) * N + r0], v21 = W[(ka + 9) * N + r0];
    float v30 = W[(ka + 8) * N + r0 + 8], v31 = W[(ka + 9) * N + r0 + 8];
    *dh = make_uint4(pkhi(v00, v01), pkhi(v10, v11), pkhi(v20, v21), pkhi(v30, v31));
    *dl = make_uint4(pklo(v00, v01), pklo(v10, v11), pklo(v20, v21), pklo(v30, v31));
}

// ---------------- k_enc_prep ----------------
__global__ __launch_bounds__(256) void k_enc_prep(
    const float* __restrict__ st, const float* __restrict__ w1, const float* __restrict__ b1,
    const float* __restrict__ w2, const float* __restrict__ b2,
    const float* __restrict__ rw1, const float* __restrict__ rw2,
    const float* __restrict__ raw, const float* __restrict__ aw1, const float* __restrict__ aw2)
{
    __shared__ float X[4 * SLEN];
    __shared__ float HD[4 * H];
    __shared__ float RED[2 * 4 * H];
    const int t = threadIdx.x;

    if (blockIdx.x >= 512) {
        int it = (blockIdx.x - 512) * 256 + t;
        if (it < 1024) {
            const int i = it, lane = i & 31, ks = (i >> 5) & 3, slot = i >> 7;
            pack_frag(rw1, 128, slot * 16 + (lane >> 2), ks * 16 + 2 * (lane & 3),
                      &g_w1fh[i], &g_w1fl[i]);
        } else if (it < 5120) {
            const int i = it - 1024, lane = i & 31, ks = (i >> 5) & 7, slot = i >> 8;
            pack_frag(rw2, 256, slot * 16 + (lane >> 2), ks * 16 + 2 * (lane & 3),
                      &g_w2fh[i], &g_w2fl[i]);
        } else if (it < 11264) {
            const int i = it - 5120, lane = i & 31, ks = (i >> 5) % 24, slot = i / 768;
            pack_frag(raw, 128, slot * 16 + (lane >> 2), ks * 16 + 2 * (lane & 3),
                      &g_wrfh[i], &g_wrfl[i]);
        } else if (it < 19456) {
            const int i = it - 11264, lane = i & 31, ks = (i >> 5) & 31, slot = i >> 10;
            pack_frag(aw1, 128, slot * 16 + (lane >> 2), ks * 16 + 2 * (lane & 3),
                      &g_wa1fh[i], &g_wa1fl[i]);
        } else {
            const int i = it - 19456, lane = i & 31, ks = (i >> 5) & 7, slot = i >> 8;
            pack_frag(aw2, 256, slot * 16 + (lane >> 2), ks * 16 + 2 * (lane & 3),
                      &g_wa2fh[i], &g_wa2fl[i]);
        }
        return;
    }

    const int row0 = blockIdx.x * 4;
    for (int i = t; i < 4 * SLEN; i += 256) X[i] = st[(size_t)row0 * SLEN + i];
    __syncthreads();
    const int h = t & 127, kh = t >> 7;
    {
        float acc[4] = {0.f, 0.f, 0.f, 0.f};
        const float4* X4 = (const float4*)X;
        const int k0 = kh * 128;
#pragma unroll 4
        for (int k = k0; k < k0 + 128; k += 4) {
            float w0 = w1[k * H + h], wA = w1[(k + 1) * H + h], wB = w1[(k + 2) * H + h], wC = w1[(k + 3) * H + h];
#pragma unroll
            for (int j = 0; j < 4; j++) {
                float4 x = X4[j * (SLEN / 4) + (k >> 2)];
                acc[j] = fmaf(x.x, w0, acc[j]); acc[j] = fmaf(x.y, wA, acc[j]);
                acc[j] = fmaf(x.z, wB, acc[j]); acc[j] = fmaf(x.w, wC, acc[j]);
            }
        }
#pragma unroll
        for (int j = 0; j < 4; j++) RED[(kh * 4 + j) * H + h] = acc[j];
    }
    __syncthreads();
    for (int idx = t; idx < 4 * H; idx += 256)
        HD[idx] = fmaxf(RED[idx] + RED[4 * H + idx] + b1[idx & 127], 0.f);
    __syncthreads();
    {
        const int rb = kh * 2;
        float acc[2];
        const float bb = b2[h];
        acc[0] = bb; acc[1] = bb;
        const float4* H4 = (const float4*)HD;
#pragma unroll 4
        for (int k = 0; k < H; k += 4) {
            float w0 = w2[k * H + h], wA = w2[(k + 1) * H + h], wB = w2[(k + 2) * H + h], wC = w2[(k + 3) * H + h];
#pragma unroll
            for (int j = 0; j < 2; j++) {
                float4 x = H4[(rb + j) * (H / 4) + (k >> 2)];
                acc[j] = fmaf(x.x, w0, acc[j]); acc[j] = fmaf(x.y, wA, acc[j]);
                acc[j] = fmaf(x.z, wB, acc[j]); acc[j] = fmaf(x.w, wC, acc[j]);
            }
        }
#pragma unroll
        for (int j = 0; j < 2; j++) g_s1[(size_t)(row0 + rb + j) * H + h] = fmaxf(acc[j], 0.f);
    }
}

// ---------------- k_smm ----------------
__global__ __launch_bounds__(256) void k_smm(const float* __restrict__ w1)
{
    __shared__ float S[16 * 128];
    const int b = blockIdx.x >> 2, j0 = (blockIdx.x & 3) * 16, t = threadIdx.x;
    for (int i = t; i < 16 * 128; i += 256)
        S[i] = g_s1[(size_t)b * 8192 + (size_t)j0 * 128 + i];
    __syncthreads();
    const int c = t & 127, jh = t >> 7;
    float acc[8];
#pragma unroll
    for (int j = 0; j < 8; j++) acc[j] = 0.f;
    const float4* S4 = (const float4*)S;
#pragma unroll 2
    for (int k4 = 0; k4 < 32; k4++) {
        const int k = 4 * k4;
        float w0 = w1[(64 + k) * 128 + c], wA = w1[(65 + k) * 128 + c];
        float wB = w1[(66 + k) * 128 + c], wC = w1[(67 + k) * 128 + c];
#pragma unroll
        for (int j = 0; j < 8; j++) {
            float4 s = S4[(jh * 8 + j) * 32 + k4];
            acc[j] = fmaf(s.x, w0, acc[j]); acc[j] = fmaf(s.y, wA, acc[j]);
            acc[j] = fmaf(s.z, wB, acc[j]); acc[j] = fmaf(s.w, wC, acc[j]);
        }
    }
#pragma unroll
    for (int j = 0; j < 8; j++)
        g_Cs[(size_t)b * 8192 + c * 64 + j0 + jh * 8 + j] = acc[j];
}

// ---------------- k_rel: round-robin accumulator MMA order ----------------
#define XS 72
#define HTS 72
#define SM_REL 55552

// interleaved: term-k for both accs before term-k+1 (breaks RAW chains)
#define DO6(q, BH, BL) \
    MMA4(ac[q], ah, BH[0], BH[1]);     MMA4(ac[q + 1], ah, BH[2], BH[3]); \
    MMA4(ac[q], ah, BL[0], BL[1]);     MMA4(ac[q + 1], ah, BL[2], BL[3]); \
    MMA4(ac[q], alr, BH[0], BH[1]);    MMA4(ac[q + 1], alr, BH[2], BH[3]);

#define DO12(q, BH, BL) \
    MMA4(acM[q], aha, BH[0], BH[1]);   MMA4(acX[q], ahb, BH[0], BH[1]); \
    MMA4(acM[q + 1], aha, BH[2], BH[3]); MMA4(acX[q + 1], ahb, BH[2], BH[3]); \
    MMA4(acM[q], aha, BL[0], BL[1]);   MMA4(acX[q], ahb, BL[0], BL[1]); \
    MMA4(acM[q + 1], aha, BL[2], BL[3]); MMA4(acX[q + 1], ahb, BL[2], BL[3]); \
    MMA4(acM[q], ala, BH[0], BH[1]);   MMA4(acX[q], alb, BH[0], BH[1]); \
    MMA4(acM[q + 1], ala, BH[2], BH[3]); MMA4(acX[q + 1], alb, BH[2], BH[3]);

__global__ __launch_bounds__(256, 2) void k_rel(
    const float* __restrict__ rel, const float* __restrict__ alive,
    const float* __restrict__ b1, const float* __restrict__ b2,
    const int* __restrict__ agp)
{
    extern __shared__ unsigned char smem[];
    __nv_bfloat16* XH = (__nv_bfloat16*)smem;
    __nv_bfloat16* XL = (__nv_bfloat16*)(smem + 9216);
    __nv_bfloat16* HTh = (__nv_bfloat16*)(smem + 18432);
    __nv_bfloat16* HTl = (__nv_bfloat16*)(smem + 36864);
    float* sal = (float*)(smem + 55296);

    const int tid = threadIdx.x, w = tid >> 5, l = tid & 31, g = l >> 2, t4 = l & 3;
    const int bi = blockIdx.x, b = bi >> 6, i = bi & 63;
    if (tid < 64) sal[tid] = alive[b * 64 + tid];

    const int sel = l >> 3, lr = l & 7;
    const uint32_t xrow = (uint32_t)(((lr + ((sel >> 1) << 3)) * XS + ((sel & 1) << 3)) * 2);
    const uint32_t hrow = (uint32_t)(((lr + ((sel & 1) << 3)) * HTS + ((sel >> 1) << 3)) * 2);
    const uint32_t xh_b = s2u(XH), xl_b = s2u(XL), hh_b = s2u(HTh), hl_b = s2u(HTl);

    {
        const float4* rr4 = (const float4*)(rel + (size_t)bi * 4096);
        for (int idx = tid; idx < 1024; idx += 256) {
            const int j = idx >> 4, k4 = idx & 15;
            float4 v = rr4[idx];
            *(uint2*)(XH + j * XS + k4 * 4) = make_uint2(pkhi(v.x, v.y), pkhi(v.z, v.w));
            *(uint2*)(XL + j * XS + k4 * 4) = make_uint2(pklo(v.x, v.y), pklo(v.z, v.w));
        }
    }
    const int r0 = w * 16 + g;
    float2 csA[8], csB[8];
    {
        const float* pA = g_Cs + (size_t)b * 8192 + r0 * 64;
        const float* pB = pA + 8 * 64;
#pragma unroll
        for (int n = 0; n < 8; n++) {
            csA[n] = *(const float2*)(pA + n * 8 + 2 * t4);
            csB[n] = *(const float2*)(pB + n * 8 + 2 * t4);
        }
    }
    __syncthreads();

    float ac[8][4];
#pragma unroll
    for (int n = 0; n < 8; n++) { ac[n][0] = 0.f; ac[n][1] = 0.f; ac[n][2] = 0.f; ac[n][3] = 0.f; }
#pragma unroll
    for (int ks = 0; ks < 4; ks++) {
        const uint4 AH = g_w1fh[(w * 4 + ks) * 32 + l];
        const uint4 AL = g_w1fl[(w * 4 + ks) * 32 + l];
        const uint32_t ah[4] = {AH.x, AH.y, AH.z, AH.w};
        const uint32_t alr[4] = {AL.x, AL.y, AL.z, AL.w};
        const uint32_t kb = (uint32_t)(ks * 32);
        uint32_t bh0[4], bl0[4], bh1[4], bl1[4];
        LDSM4(bh0, xh_b + kb + xrow);
        LDSM4(bl0, xl_b + kb + xrow);
        LDSM4(bh1, xh_b + (uint32_t)(16 * XS * 2) + kb + xrow);
        LDSM4(bl1, xl_b + (uint32_t)(16 * XS * 2) + kb + xrow);
        DO6(0, bh0, bl0)
        DO6(2, bh1, bl1)
        LDSM4(bh0, xh_b + (uint32_t)(32 * XS * 2) + kb + xrow);
        LDSM4(bl0, xl_b + (uint32_t)(32 * XS * 2) + kb + xrow);
        LDSM4(bh1, xh_b + (uint32_t)(48 * XS * 2) + kb + xrow);
        LDSM4(bl1, xl_b + (uint32_t)(48 * XS * 2) + kb + xrow);
        DO6(4, bh0, bl0)
        DO6(6, bh1, bl1)
    }
    {
        const float bA = b1[r0], bB = b1[r0 + 8];
#pragma unroll
        for (int n = 0; n < 8; n++) {
            const int j0 = n * 8 + 2 * t4;
            float v0 = fmaxf(ac[n][0] + csA[n].x + bA, 0.f);
            float v1 = fmaxf(ac[n][1] + csA[n].y + bA, 0.f);
            float v2 = fmaxf(ac[n][2] + csB[n].x + bB, 0.f);
            float v3 = fmaxf(ac[n][3] + csB[n].y + bB, 0.f);
            *(uint32_t*)(HTh + r0 * HTS + j0) = pkhi(v0, v1);
            *(uint32_t*)(HTl + r0 * HTS + j0) = pklo(v0, v1);
            *(uint32_t*)(HTh + (r0 + 8) * HTS + j0) = pkhi(v2, v3);
            *(uint32_t*)(HTl + (r0 + 8) * HTS + j0) = pklo(v2, v3);
        }
    }
    __syncthreads();

    float acM[8][4], acX[8][4];
#pragma unroll
    for (int n = 0; n < 8; n++) {
        acM[n][0] = 0.f; acM[n][1] = 0.f; acM[n][2] = 0.f; acM[n][3] = 0.f;
        acX[n][0] = 0.f; acX[n][1] = 0.f; acX[n][2] = 0.f; acX[n][3] = 0.f;
    }
#pragma unroll 1
    for (int ks = 0; ks < 8; ks++) {
        const uint4 AHa = g_w2fh[(w * 8 + ks) * 32 + l];
        const uint4 ALa = g_w2fl[(w * 8 + ks) * 32 + l];
        const uint4 AHb = g_w2fh[((8 + w) * 8 + ks) * 32 + l];
        const uint4 ALb = g_w2fl[((8 + w) * 8 + ks) * 32 + l];
        const uint32_t aha[4] = {AHa.x, AHa.y, AHa.z, AHa.w};
        const uint32_t ala[4] = {ALa.x, ALa.y, ALa.z, ALa.w};
        const uint32_t ahb[4] = {AHb.x, AHb.y, AHb.z, AHb.w};
        const uint32_t alb[4] = {ALb.x, ALb.y, ALb.z, ALb.w};
        const uint32_t kb = (uint32_t)(ks * 16 * HTS * 2);
        uint32_t bh0[4], bl0[4], bh1[4], bl1[4];
        LDSM4T(bh0, hh_b + kb + hrow);
        LDSM4T(bl0, hl_b + kb + hrow);
        LDSM4T(bh1, hh_b + kb + 32 + hrow);
        LDSM4T(bl1, hl_b + kb + 32 + hrow);
        DO12(0, bh0, bl0)
        DO12(2, bh1, bl1)
        LDSM4T(bh0, hh_b + kb + 64 + hrow);
        LDSM4T(bl0, hl_b + kb + 64 + hrow);
        LDSM4T(bh1, hh_b + kb + 96 + hrow);
        LDSM4T(bl1, hl_b + kb + 96 + hrow);
        DO12(4, bh0, bl0)
        DO12(6, bh1, bl1)
    }
    {
        const int rrA = w * 16 + g;
        const int rrB = 128 + w * 16 + g;
        const int gag = *agp;
        const bool isag = (i == gag);
        const float bMA = b2[rrA], bMB = b2[rrA + 8];
        const float bXA = b2[rrB], bXB = b2[rrB + 8];
        float s0 = 0.f, s1 = 0.f, t0 = 0.f, t1 = 0.f;
        float* rg = g_ragent + (size_t)(b * 64) * 256;
#pragma unroll
        for (int n = 0; n < 8; n++) {
            const int j0 = n * 8 + 2 * t4;
            const float al0 = sal[j0], al1 = sal[j0 + 1];
            float m0 = fmaxf(acM[n][0] + bMA, 0.f), m1 = fmaxf(acM[n][1] + bMA, 0.f);
            float m2 = fmaxf(acM[n][2] + bMB, 0.f), m3 = fmaxf(acM[n][3] + bMB, 0.f);
            float x0 = fmaxf(acX[n][0] + bXA, 0.f), x1 = fmaxf(acX[n][1] + bXA, 0.f);
            float x2 = fmaxf(acX[n][2] + bXB, 0.f), x3 = fmaxf(acX[n][3] + bXB, 0.f);
            if (isag) {
                rg[(size_t)j0 * 256 + rrA] = m0;
                rg[(size_t)(j0 + 1) * 256 + rrA] = m1;
                rg[(size_t)j0 * 256 + rrA + 8] = m2;
                rg[(size_t)(j0 + 1) * 256 + rrA + 8] = m3;
                rg[(size_t)j0 * 256 + rrB] = x0;
                rg[(size_t)(j0 + 1) * 256 + rrB] = x1;
                rg[(size_t)j0 * 256 + rrB + 8] = x2;
                rg[(size_t)(j0 + 1) * 256 + rrB + 8] = x3;
            }
            s0 += m0 * al0 + m1 * al1;
            s1 += m2 * al0 + m3 * al1;
            t0 = fmaxf(t0, fmaxf(x0 * al0, x1 * al1));
            t1 = fmaxf(t1, fmaxf(x2 * al0, x3 * al1));
        }
        s0 += __shfl_xor_sync(0xffffffffu, s0, 1); s0 += __shfl_xor_sync(0xffffffffu, s0, 2);
        s1 += __shfl_xor_sync(0xffffffffu, s1, 1); s1 += __shfl_xor_sync(0xffffffffu, s1, 2);
        t0 = fmaxf(t0, __shfl_xor_sync(0xffffffffu, t0, 1)); t0 = fmaxf(t0, __shfl_xor_sync(0xffffffffu, t0, 2));
        t1 = fmaxf(t1, __shfl_xor_sync(0xffffffffu, t1, 1)); t1 = fmaxf(t1, __shfl_xor_sync(0xffffffffu, t1, 2));
        if (t4 == 0) {
            g_pooled[(size_t)bi * 256 + rrA] = s0 * (1.f / 64.f);
            g_pooled[(size_t)bi * 256 + rrA + 8] = s1 * (1.f / 64.f);
            g_pooled[(size_t)bi * 256 + rrB] = t0;
            g_pooled[(size_t)bi * 256 + rrB + 8] = t1;
        }
    }
}

// ---------------- k_tail: 512 thr, split-K warp pairs, prefetch, RR MMA order ----------------
#define XT 520
#define S2S 132
#define HT2 24
#define SM_TAIL 88848

__global__ __launch_bounds__(512, 1) void k_tail(
    const float* __restrict__ raw, const float* __restrict__ rab,
    const float* __restrict__ ab1, const float* __restrict__ ab2,
    const int* __restrict__ agp)
{
    extern __shared__ unsigned char smem[];
    __nv_bfloat16* XH = (__nv_bfloat16*)smem;
    __nv_bfloat16* XL = (__nv_bfloat16*)(smem + 16640);
    float* S2f = (float*)(smem + 33280);
    __nv_bfloat16* HTh = (__nv_bfloat16*)(smem + 42256);
    __nv_bfloat16* HTl = (__nv_bfloat16*)(smem + 48400);
    float* RED = (float*)(smem + 54544);
    float* AG = (float*)(smem + 87312);

    const int tid = threadIdx.x, w = tid >> 5, l = tid & 31, g = l >> 2, t4 = l & 3;
    const int wp = w & 7, kh2 = w >> 3;
    const int b = blockIdx.x >> 2, jg0 = (blockIdx.x & 3) * 16;
    const int gag = *agp;
    const int sel = l >> 3, lr = l & 7;
    const uint32_t xrow = (uint32_t)(((lr + ((sel >> 1) << 3)) * XT + ((sel & 1) << 3)) * 2);
    const uint32_t hrow = (uint32_t)(((lr + ((sel & 1) << 3)) * HT2 + ((sel >> 1) << 3)) * 2);
    const uint32_t xh_b = s2u(XH), xl_b = s2u(XL), hh_b = s2u(HTh), hl_b = s2u(HTl);
    const int r0 = wp * 16 + g;
    const int j0 = 2 * t4, j1 = 8 + 2 * t4;

    for (int idx = tid; idx < 16 * 32; idx += 512) {
        const int j = idx >> 5, k4 = idx & 31;
        float4 v = *(const float4*)(g_s1 + (size_t)(b * 64 + jg0 + j) * 128 + k4 * 4);
        *(uint2*)(XH + j * XT + k4 * 4) = make_uint2(pkhi(v.x, v.y), pkhi(v.z, v.w));
        *(uint2*)(XL + j * XT + k4 * 4) = make_uint2(pklo(v.x, v.y), pklo(v.z, v.w));
    }
    for (int idx = tid; idx < 16 * 64; idx += 512) {
        const int j = idx >> 6, k4 = idx & 63;
        float4 v = *(const float4*)(g_pooled + (size_t)(b * 64 + j + jg0) * 256 + k4 * 4);
        *(uint2*)(XH + j * XT + 128 + k4 * 4) = make_uint2(pkhi(v.x, v.y), pkhi(v.z, v.w));
        *(uint2*)(XL + j * XT + 128 + k4 * 4) = make_uint2(pklo(v.x, v.y), pklo(v.z, v.w));
    }
    if (tid < 96) {
        float4 v = (tid < 32)
            ? *(const float4*)(g_s1 + (size_t)(b * 64 + gag) * 128 + tid * 4)
            : *(const float4*)(g_pooled + (size_t)(b * 64 + gag) * 256 + (tid - 32) * 4);
        *(float4*)(AG + tid * 4) = v;
    }
    __syncthreads();

    // ---- ra GEMM: K=384, 12 ks per warp-half, prefetched, RR order ----
    {
        float a0[4] = {0.f, 0.f, 0.f, 0.f}, a1[4] = {0.f, 0.f, 0.f, 0.f};
        const int ks0 = kh2 * 12;
        uint4 AH = g_wrfh[(wp * 24 + ks0) * 32 + l];
        uint4 AL = g_wrfl[(wp * 24 + ks0) * 32 + l];
#pragma unroll 1
        for (int ks = ks0; ks < ks0 + 12; ks++) {
            uint4 AHn = AH, ALn = AL;
            if (ks + 1 < ks0 + 12) {
                AHn = g_wrfh[(wp * 24 + ks + 1) * 32 + l];
                ALn = g_wrfl[(wp * 24 + ks + 1) * 32 + l];
            }
            const uint32_t ah[4] = {AH.x, AH.y, AH.z, AH.w};
            const uint32_t alr[4] = {AL.x, AL.y, AL.z, AL.w};
            uint32_t bh[4], bl[4];
            LDSM4(bh, xh_b + (uint32_t)(ks * 32) + xrow);
            LDSM4(bl, xl_b + (uint32_t)(ks * 32) + xrow);
            MMA4(a0, ah, bh[0], bh[1]);  MMA4(a1, ah, bh[2], bh[3]);
            MMA4(a0, ah, bl[0], bl[1]);  MMA4(a1, ah, bl[2], bl[3]);
            MMA4(a0, alr, bh[0], bh[1]); MMA4(a1, alr, bh[2], bh[3]);
            AH = AHn; AL = ALn;
        }
        float* RP = RED + kh2 * 2048;
        RP[j0 * 128 + r0] = a0[0];       RP[(j0 + 1) * 128 + r0] = a0[1];
        RP[j0 * 128 + r0 + 8] = a0[2];   RP[(j0 + 1) * 128 + r0 + 8] = a0[3];
        RP[j1 * 128 + r0] = a1[0];       RP[(j1 + 1) * 128 + r0] = a1[1];
        RP[j1 * 128 + r0 + 8] = a1[2];   RP[(j1 + 1) * 128 + r0 + 8] = a1[3];
    }
    {
        const int h = tid & 127, kh = tid >> 7;
        float acc = 0.f;
        const int k0 = kh * 96;
#pragma unroll 4
        for (int k = k0; k < k0 + 96; k++)
            acc = fmaf(AG[k], raw[k * 128 + h], acc);
        RED[4096 + kh * 128 + h] = acc;
    }
    __syncthreads();
    for (int idx = tid; idx < 2048; idx += 512) {
        const int c = idx >> 4, j = idx & 15;
        S2f[j * S2S + c] = fmaxf(RED[j * 128 + c] + RED[2048 + j * 128 + c] + rab[c], 0.f);
    }
    if (tid < 128)
        S2f[16 * S2S + tid] = fmaxf(RED[4096 + tid] + RED[4224 + tid]
                                  + RED[4352 + tid] + RED[4480 + tid] + rab[tid], 0.f);
    __syncthreads();

    for (int idx = tid; idx < 16 * 64; idx += 512) {
        const int j = idx >> 6, k4 = idx & 63;
        float4 v = *(const float4*)(g_ragent + (size_t)(b * 64 + jg0 + j) * 256 + k4 * 4);
        *(uint2*)(XH + j * XT + k4 * 4) = make_uint2(pkhi(v.x, v.y), pkhi(v.z, v.w));
        *(uint2*)(XL + j * XT + k4 * 4) = make_uint2(pklo(v.x, v.y), pklo(v.z, v.w));
    }
    for (int idx = tid; idx < 16 * 32; idx += 512) {
        const int j = idx >> 5, k4 = idx & 31;
        float4 v = *(const float4*)(S2f + j * S2S + k4 * 4);
        *(uint2*)(XH + j * XT + 256 + k4 * 4) = make_uint2(pkhi(v.x, v.y), pkhi(v.z, v.w));
        *(uint2*)(XL + j * XT + 256 + k4 * 4) = make_uint2(pklo(v.x, v.y), pklo(v.z, v.w));
        *(float4*)(g_s2 + (size_t)(b * 64 + jg0 + j) * 128 + k4 * 4) = v;
        float4 va = *(const float4*)(S2f + 16 * S2S + k4 * 4);
        *(uint2*)(XH + j * XT + 384 + k4 * 4) = make_uint2(pkhi(va.x, va.y), pkhi(va.z, va.w));
        *(uint2*)(XL + j * XT + 384 + k4 * 4) = make_uint2(pklo(va.x, va.y), pklo(va.z, va.w));
    }
    __syncthreads();

    // ---- ae layer 1: K=512, 16 ks per warp-half, prefetched, RR order ----
    {
        float a0[4] = {0.f, 0.f, 0.f, 0.f}, a1[4] = {0.f, 0.f, 0.f, 0.f};
        const int ks0 = kh2 * 16;
        uint4 AH = g_wa1fh[(wp * 32 + ks0) * 32 + l];
        uint4 AL = g_wa1fl[(wp * 32 + ks0) * 32 + l];
#pragma unroll 1
        for (int ks = ks0; ks < ks0 + 16; ks++) {
            uint4 AHn = AH, ALn = AL;
            if (ks + 1 < ks0 + 16) {
                AHn = g_wa1fh[(wp * 32 + ks + 1) * 32 + l];
                ALn = g_wa1fl[(wp * 32 + ks + 1) * 32 + l];
            }
            const uint32_t ah[4] = {AH.x, AH.y, AH.z, AH.w};
            const uint32_t alr[4] = {AL.x, AL.y, AL.z, AL.w};
            uint32_t bh[4], bl[4];
            LDSM4(bh, xh_b + (uint32_t)(ks * 32) + xrow);
            LDSM4(bl, xl_b + (uint32_t)(ks * 32) + xrow);
            MMA4(a0, ah, bh[0], bh[1]);  MMA4(a1, ah, bh[2], bh[3]);
            MMA4(a0, ah, bl[0], bl[1]);  MMA4(a1, ah, bl[2], bl[3]);
            MMA4(a0, alr, bh[0], bh[1]); MMA4(a1, alr, bh[2], bh[3]);
            AH = AHn; AL = ALn;
        }
        float* RP = RED + kh2 * 2048;
        RP[j0 * 128 + r0] = a0[0];       RP[(j0 + 1) * 128 + r0] = a0[1];
        RP[j0 * 128 + r0 + 8] = a0[2];   RP[(j0 + 1) * 128 + r0 + 8] = a0[3];
        RP[j1 * 128 + r0] = a1[0];       RP[(j1 + 1) * 128 + r0] = a1[1];
        RP[j1 * 128 + r0 + 8] = a1[2];   RP[(j1 + 1) * 128 + r0 + 8] = a1[3];
    }
    __syncthreads();
    for (int idx = tid; idx < 2048; idx += 512) {
        const int c = idx >> 4, j = idx & 15;
        float v = fmaxf(RED[j * 128 + c] + RED[2048 + j * 128 + c] + ab1[c], 0.f);
        __nv_bfloat16 hh = __float2bfloat16(v);
        HTh[c * HT2 + j] = hh;
        HTl[c * HT2 + j] = __float2bfloat16(v - __bfloat162float(hh));
    }
    __syncthreads();

    // ---- ae layer 2: K=128, 4 ks per warp-half, prefetched, RR order ----
    {
        float acM0[4] = {0.f, 0.f, 0.f, 0.f}, acM1[4] = {0.f, 0.f, 0.f, 0.f};
        float acX0[4] = {0.f, 0.f, 0.f, 0.f}, acX1[4] = {0.f, 0.f, 0.f, 0.f};
        const int ks0 = kh2 * 4;
        uint4 AHa = g_wa2fh[(wp * 8 + ks0) * 32 + l];
        uint4 ALa = g_wa2fl[(wp * 8 + ks0) * 32 + l];
        uint4 AHb = g_wa2fh[((8 + wp) * 8 + ks0) * 32 + l];
        uint4 ALb = g_wa2fl[((8 + wp) * 8 + ks0) * 32 + l];
#pragma unroll 1
        for (int ks = ks0; ks < ks0 + 4; ks++) {
            uint4 AHan = AHa, ALan = ALa, AHbn = AHb, ALbn = ALb;
            if (ks + 1 < ks0 + 4) {
                AHan = g_wa2fh[(wp * 8 + ks + 1) * 32 + l];
                ALan = g_wa2fl[(wp * 8 + ks + 1) * 32 + l];
                AHbn = g_wa2fh[((8 + wp) * 8 + ks + 1) * 32 + l];
                ALbn = g_wa2fl[((8 + wp) * 8 + ks + 1) * 32 + l];
            }
            const uint32_t aha[4] = {AHa.x, AHa.y, AHa.z, AHa.w};
            const uint32_t ala[4] = {ALa.x, ALa.y, ALa.z, ALa.w};
            const uint32_t ahb[4] = {AHb.x, AHb.y, AHb.z, AHb.w};
            const uint32_t alb[4] = {ALb.x, ALb.y, ALb.z, ALb.w};
            uint32_t bh[4], bl[4];
            LDSM4T(bh, hh_b + (uint32_t)(ks * 16 * HT2 * 2) + hrow);
            LDSM4T(bl, hl_b + (uint32_t)(ks * 16 * HT2 * 2) + hrow);
            MMA4(acM0, aha, bh[0], bh[1]);  MMA4(acX0, ahb, bh[0], bh[1]);
            MMA4(acM1, aha, bh[2], bh[3]);  MMA4(acX1, ahb, bh[2], bh[3]);
            MMA4(acM0, aha, bl[0], bl[1]);  MMA4(acX0, ahb, bl[0], bl[1]);
            MMA4(acM1, aha, bl[2], bl[3]);  MMA4(acX1, ahb, bl[2], bl[3]);
            MMA4(acM0, ala, bh[0], bh[1]);  MMA4(acX0, alb, bh[0], bh[1]);
            MMA4(acM1, ala, bh[2], bh[3]);  MMA4(acX1, alb, bh[2], bh[3]);
            AHa = AHan; ALa = ALan; AHb = AHbn; ALb = ALbn;
        }
        float* RP = RED + kh2 * 4096;
        RP[j0 * 256 + r0] = acM0[0];         RP[(j0 + 1) * 256 + r0] = acM0[1];
        RP[j0 * 256 + r0 + 8] = acM0[2];     RP[(j0 + 1) * 256 + r0 + 8] = acM0[3];
        RP[j1 * 256 + r0] = acM1[0];         RP[(j1 + 1) * 256 + r0] = acM1[1];
        RP[j1 * 256 + r0 + 8] = acM1[2];     RP[(j1 + 1) * 256 + r0 + 8] = acM1[3];
        RP[j0 * 256 + 128 + r0] = acX0[0];   RP[(j0 + 1) * 256 + 128 + r0] = acX0[1];
        RP[j0 * 256 + 128 + r0 + 8] = acX0[2]; RP[(j0 + 1) * 256 + 128 + r0 + 8] = acX0[3];
        RP[j1 * 256 + 128 + r0] = acX1[0];   RP[(j1 + 1) * 256 + 128 + r0] = acX1[1];
        RP[j1 * 256 + 128 + r0 + 8] = acX1[2]; RP[(j1 + 1) * 256 + 128 + r0 + 8] = acX1[3];
    }
    __syncthreads();
    {
        float* ae = g_aeT + (size_t)b * 256 * 64 + jg0;
        for (int idx = tid; idx < 4096; idx += 512) {
            const int c = idx >> 4, j = idx & 15;
            float v = fmaxf(RED[j * 256 + c] + RED[4096 + j * 256 + c] + ab2[c], 0.f);
            ae[c * 64 + j] = v;
        }
    }
}

// ---------------- k_final (g_aeT layout) ----------------
__global__ __launch_bounds__(256) void k_final(
    const float* __restrict__ action_embed, const int* __restrict__ action,
    const int* __restrict__ agp, float* __restrict__ out)
{
    const int b = blockIdx.x, t = threadIdx.x;
    const int h = t & 127, jp = t >> 7;
    const int a = action[b], g = *agp;
    const float sel = (a < E) ? action_embed[a * H + h]
                              : g_aeT[((size_t)b * 256 + h) * 64 + (a - E)];
    float* out_state = out;
    float* out_sel = out + (size_t)B * A * H;
    float* out_ps = out_sel + (size_t)B * H;
    if (jp == 0) out_sel[b * H + h] = sel;
    for (int j = jp; j < A; j += 2) {
        float st = g_s2[((size_t)b * A + j) * H + h];
        float ps = 0.f;
        if (a == E + j) ps = g_aeT[((size_t)b * 256 + H + h) * 64 + j];
        if (j == g) st += sel;
        out_ps[((size_t)b * A + j) * H + h] = ps;
        out_state[((size_t)b * A + j) * H + h] = st + ps;
    }
}

// ---------------- launcher ----------------
extern "C" void kernel_launch(void* const* d_in, const int* in_sizes, int n_in,
                              void* d_out, int out_size)
{
    const float* states       = (const float*)d_in[0];
    const float* relations    = (const float*)d_in[1];
    const float* alive_mask   = (const float*)d_in[2];
    const float* se_w1        = (const float*)d_in[3];
    const float* se_b1        = (const float*)d_in[4];
    const float* se_w2        = (const float*)d_in[5];
    const float* se_b2        = (const float*)d_in[6];
    const float* re_w1        = (const float*)d_in[7];
    const float* re_b1        = (const float*)d_in[8];
    const float* re_w2        = (const float*)d_in[9];
    const float* re_b2        = (const float*)d_in[10];
    const float* ra_w         = (const float*)d_in[11];
    const float* ra_b         = (const float*)d_in[12];
    const float* ae_w1        = (const float*)d_in[13];
    const float* ae_b1        = (const float*)d_in[14];
    const float* ae_w2        = (const float*)d_in[15];
    const float* ae_b2        = (const float*)d_in[16];
    const float* action_embed = (const float*)d_in[17];
    const int*   action       = (const int*)d_in[19];
    const int*   agent_id     = (const int*)d_in[20];
    float* out = (float*)d_out;

    static bool attr = false;
    if (!attr) {
        cudaFuncSetAttribute(k_rel, cudaFuncAttributeMaxDynamicSharedMemorySize, SM_REL);
        cudaFuncSetAttribute(k_tail, cudaFuncAttributeMaxDynamicSharedMemorySize, SM_TAIL);
        attr = true;
    }

    k_enc_prep<<<604, 256>>>(states, se_w1, se_b1, se_w2, se_b2,
                             re_w1, re_w2, ra_w, ae_w1, ae_w2);
    k_smm<<<128, 256>>>(re_w1);
    k_rel<<<B * A, 256, SM_REL>>>(relations, alive_mask, re_b1, re_b2, agent_id);
    k_tail<<<B * 4, 512, SM_TAIL>>>(ra_w, ra_b, ae_b1, ae_b2, agent_id);
    k_final<<<B, 256>>>(action_embed, action, agent_id, out);
}